// round 14
// baseline (speedup 1.0000x reference)
#include <cuda_runtime.h>
#include <cuda_bf16.h>
#include <cuda_fp16.h>
#include <cstdint>

// ---------------------------------------------------------------- constants
#define T_   1024
#define BZ   4
#define E_   1024
#define NH   16
#define HD   64
#define BH   64
#define SLEN 1025
#define M_   4096
#define LOG2E 1.44269504f
#define QSCALE2 (0.00390625f * LOG2E)
#define GATE_SC (256.0f / LOG2E)

// GEMM tiling: CTA 256x128, 16 warps (8x2), warp 32x64, K-chunk 32 bf16
#define GROWB 80
#define SA_SZ (256 * GROWB)
#define SB_SZ (128 * GROWB)
#define SB_OFF (2 * SA_SZ)
#define STAGE (2 * SA_SZ + 2 * SB_SZ)   // 61440 (heavy)
#define LSB_OFF SA_SZ
#define LSTAGE (SA_SZ + SB_SZ)          // 30720 (light)
#define GEMM_SMEM (3 * STAGE)           // 184320

// attention smem: 128-row Q tile + gates + pb row + 2 stages x {KH, VH, VL}
#define AROW  144
#define ATILE (64 * AROW)               // 9216
#define A_GT  18432                     // gate[128], gws[64], misc[2]
#define A_PB  19456                     // pb row: 2048 f32 = 8192 B
#define A_ST  27648
#define A_STB (3 * ATILE)               // 27648
#define ATTN_SMEM (A_ST + 2 * A_STB)    // 82944

#define KVSZ ((size_t)BH * SLEN * HD + 8192)

// ---------------------------------------------------------------- scratch
__device__ __nv_bfloat16 g_Qh[(size_t)BH * T_ * HD];
__device__ __nv_bfloat16 g_Kh[KVSZ];
__device__ __half g_Vh16[KVSZ], g_Vl16[KVSZ];
__device__ float g_pb[(size_t)NH * 2048];

__device__ __nv_bfloat16 g_Ahi[(size_t)M_ * E_];
__device__ __nv_bfloat16 g_Alo[(size_t)M_ * E_];
__device__ __nv_bfloat16 g_Whi[4][(size_t)E_ * E_];
__device__ __nv_bfloat16 g_Wlo[4][(size_t)E_ * E_];

// ---------------------------------------------------------------- helpers
__device__ __forceinline__ uint32_t cvta_smem(const void* p) {
    uint32_t a;
    asm("{ .reg .u64 t; cvta.to.shared.u64 t, %1; cvt.u32.u64 %0, t; }"
        : "=r"(a) : "l"(p));
    return a;
}

#define CP16(dst, src) \
    asm volatile("cp.async.cg.shared.global [%0], [%1], 16;" \
        :: "r"(dst), "l"(src) : "memory")
#define CPCOMMIT() asm volatile("cp.async.commit_group;" ::: "memory")
#define CPWAIT1()  asm volatile("cp.async.wait_group 1;" ::: "memory")
#define CPWAIT0()  asm volatile("cp.async.wait_group 0;" ::: "memory")

__device__ __forceinline__ void ldsm_x4(uint32_t r[4], uint32_t addr) {
    asm volatile(
        "ldmatrix.sync.aligned.m8n8.x4.shared.b16 {%0,%1,%2,%3}, [%4];"
        : "=r"(r[0]), "=r"(r[1]), "=r"(r[2]), "=r"(r[3]) : "r"(addr));
}
__device__ __forceinline__ void ldsm_x4_t(uint32_t r[4], uint32_t addr) {
    asm volatile(
        "ldmatrix.sync.aligned.m8n8.x4.trans.shared.b16 {%0,%1,%2,%3}, [%4];"
        : "=r"(r[0]), "=r"(r[1]), "=r"(r[2]), "=r"(r[3]) : "r"(addr));
}

// bf16 mma
__device__ __forceinline__ void mma16816(float c[4], const uint32_t a[4],
                                         uint32_t b0, uint32_t b1) {
    asm volatile(
        "mma.sync.aligned.m16n8k16.row.col.f32.bf16.bf16.f32 "
        "{%0,%1,%2,%3}, {%4,%5,%6,%7}, {%8,%9}, {%0,%1,%2,%3};"
        : "+f"(c[0]), "+f"(c[1]), "+f"(c[2]), "+f"(c[3])
        : "r"(a[0]), "r"(a[1]), "r"(a[2]), "r"(a[3]), "r"(b0), "r"(b1));
}
// fp16 mma
__device__ __forceinline__ void mma16816h(float c[4], const uint32_t a[4],
                                          uint32_t b0, uint32_t b1) {
    asm volatile(
        "mma.sync.aligned.m16n8k16.row.col.f32.f16.f16.f32 "
        "{%0,%1,%2,%3}, {%4,%5,%6,%7}, {%8,%9}, {%0,%1,%2,%3};"
        : "+f"(c[0]), "+f"(c[1]), "+f"(c[2]), "+f"(c[3])
        : "r"(a[0]), "r"(a[1]), "r"(a[2]), "r"(a[3]), "r"(b0), "r"(b1));
}

__device__ __forceinline__ float ex2f(float x) {
    float y;
    asm("ex2.approx.f32 %0, %1;" : "=f"(y) : "f"(x));
    return y;
}

__device__ __forceinline__ uint32_t pack2(float x, float y) {
    __nv_bfloat162 t = __float22bfloat162_rn(make_float2(x, y));
    return *reinterpret_cast<uint32_t*>(&t);
}
__device__ __forceinline__ uint32_t pack2h(float x, float y) {
    __half2 t = __float22half2_rn(make_float2(x, y));
    return *reinterpret_cast<uint32_t*>(&t);
}

// packed bf16x2 split
__device__ __forceinline__ void split2(float x, float y,
                                       uint32_t& hi, uint32_t& lo) {
    __nv_bfloat162 h2 = __float22bfloat162_rn(make_float2(x, y));
    float2 hf = __bfloat1622float2(h2);
    __nv_bfloat162 l2 = __float22bfloat162_rn(make_float2(x - hf.x, y - hf.y));
    hi = *reinterpret_cast<uint32_t*>(&h2);
    lo = *reinterpret_cast<uint32_t*>(&l2);
}
// packed fp16x2 split
__device__ __forceinline__ void split2h(float x, float y,
                                        uint32_t& hi, uint32_t& lo) {
    __half2 h2 = __float22half2_rn(make_float2(x, y));
    float2 hf = __half22float2(h2);
    __half2 l2 = __float22half2_rn(make_float2(x - hf.x, y - hf.y));
    hi = *reinterpret_cast<uint32_t*>(&h2);
    lo = *reinterpret_cast<uint32_t*>(&l2);
}

// ---------------------------------------------------------------- prep_all
__global__ __launch_bounds__(256)
void prep_all(const float* __restrict__ query,
              const float* __restrict__ w0, const float* __restrict__ w1,
              const float* __restrict__ w2, const float* __restrict__ w3,
              const float* __restrict__ rel_emb,
              const float* __restrict__ bias_k,
              const float* __restrict__ bias_v)
{
    __shared__ float tile[32][33];
    int bid = blockIdx.x;
    int tid = threadIdx.x;

    if (bid < 4096) {
        int i = bid * 256 + tid;
        float4 v = reinterpret_cast<const float4*>(query)[i];
        uint32_t h0, l0, h1, l1;
        split2(v.x, v.y, h0, l0);
        split2(v.z, v.w, h1, l1);
        uint32_t* hp = reinterpret_cast<uint32_t*>(g_Ahi);
        uint32_t* lp = reinterpret_cast<uint32_t*>(g_Alo);
        hp[2 * i] = h0; hp[2 * i + 1] = h1;
        lp[2 * i] = l0; lp[2 * i + 1] = l1;
    } else if (bid < 8192) {
        int b2 = bid - 4096;
        int z = b2 >> 10;
        int rem = b2 & 1023;
        int bx = (rem & 31) * 32, by = (rem >> 5) * 32;
        int tx = tid & 31, ty = tid >> 5;
        const float* W = (z == 0) ? w0 : (z == 1) ? w1 : (z == 2) ? w2 : w3;
        __nv_bfloat16* hi = g_Whi[z];
        __nv_bfloat16* lo = g_Wlo[z];
        #pragma unroll
        for (int r = 0; r < 4; r++)
            tile[ty + r * 8][tx] = W[(size_t)(by + ty + r * 8) * E_ + bx + tx];
        __syncthreads();
        #pragma unroll
        for (int r = 0; r < 4; r++) {
            int n = bx + ty + r * 8, k = by + tx;
            float v = tile[tx][ty + r * 8];
            __nv_bfloat16 h = __float2bfloat16(v);
            hi[(size_t)n * E_ + k] = h;
            lo[(size_t)n * E_ + k] = __float2bfloat16(v - __bfloat162float(h));
        }
    } else {
        int i = (bid - 8192) * 256 + tid;
        if (i < 2048) {
            int rel = i - 1023;
            int bkt = rel > 0 ? 16 : 0;
            int a = rel < 0 ? -rel : rel;
            int bu;
            if (a < 8) {
                bu = a;
            } else {
                float lf = logf((float)a * 0.125f + 1e-6f)
                           * (8.0f / 2.772588722239781f);
                int large = 8 + (int)lf;
                bu = large < 15 ? large : 15;
            }
            int bucket = bkt + bu;
            #pragma unroll
            for (int h = 0; h < NH; h++)
                g_pb[h * 2048 + i] = rel_emb[bucket * NH + h] * LOG2E;
        }
        int b = i >> 10, h = (i >> 6) & 15, d = i & 63;
        int x = b * 16 + 15;
        int y = 1009 + h;
        size_t idx = ((size_t)x * SLEN + y) * HD + d;
        float kv = bias_k[h * HD + d];
        float vv = bias_v[h * HD + d];
        __half vh = __float2half(vv);
        g_Kh[idx] = __float2bfloat16(kv);
        g_Vh16[idx] = vh;
        g_Vl16[idx] = __float2half(vv - __half2float(vh));
    }
}

// ---------------------------------------------------------------- fused QKV GEMM
// grid (24, 16): bn 0-7 -> V proj (heavy, 3-term bf16 split, fp16 output)
//                bn 8-15 -> Q proj (light), bn 16-23 -> K proj (light)
__global__ __launch_bounds__(512, 1)
void gemm_qkv(const __nv_bfloat16* __restrict__ Ahi,
              const __nv_bfloat16* __restrict__ Alo,
              const float* __restrict__ q_b,
              const float* __restrict__ k_b,
              const float* __restrict__ v_b)
{
    extern __shared__ __align__(16) char sm_[];
    const int tid = threadIdx.x, lane = tid & 31, w = tid >> 5;
    const int bn = blockIdx.x, bm = blockIdx.y;
    const uint32_t smem_u = cvta_smem(sm_);

    const int wm = w >> 1, wn = w & 1;
    const int m0 = wm * 32, n0 = wn * 64;
    const int gid = lane >> 2, tig = lane & 3;
    const int mat = lane >> 3, rowin = lane & 7;
    const int a_row = rowin + (mat & 1) * 8;
    const int a_kof = (mat >> 1) * 16;
    const int b_row = rowin + (mat >> 1) * 8;
    const int b_kof = (mat & 1) * 16;

    const char* gA0 = (const char*)(Ahi + (size_t)(bm * 256) * 1024);
    const char* gA1 = (const char*)(Alo + (size_t)(bm * 256) * 1024);

    if (bn < 8) {
        // ---------------- heavy path: V projection
        const char* gB0 = (const char*)(g_Whi[2] + (size_t)(bn * 128) * 1024);
        const char* gB1 = (const char*)(g_Wlo[2] + (size_t)(bn * 128) * 1024);

        auto load_stage = [&](int it, int buf) {
            uint32_t sb = smem_u + buf * STAGE;
            const int kb = it * 64;
            #pragma unroll
            for (int i = 0; i < 6; i++) {
                int idx = tid + i * 512;
                if (idx < 2048) {
                    int tile = idx >> 10, row = (idx >> 2) & 255, c = idx & 3;
                    const char* g = (tile ? gA1 : gA0)
                                    + (size_t)row * 2048 + kb + c * 16;
                    CP16(sb + tile * SA_SZ + row * GROWB + c * 16, g);
                } else {
                    int i2 = idx - 2048;
                    int tile = i2 >> 9, row = (i2 >> 2) & 127, c = i2 & 3;
                    const char* g = (tile ? gB1 : gB0)
                                    + (size_t)row * 2048 + kb + c * 16;
                    CP16(sb + SB_OFF + tile * SB_SZ + row * GROWB + c * 16, g);
                }
            }
            CPCOMMIT();
        };

        float acc[2][8][4] = {};
        load_stage(0, 0);
        load_stage(1, 1);

        for (int it = 0; it < 32; it++) {
            int buf = it % 3;
            if (it < 31) { CPWAIT1(); } else { CPWAIT0(); }
            __syncthreads();
            uint32_t sb = smem_u + buf * STAGE;
            #pragma unroll
            for (int ks = 0; ks < 2; ks++) {
                uint32_t ahi[2][4], alo[2][4];
                #pragma unroll
                for (int mt = 0; mt < 2; mt++) {
                    uint32_t ar = sb + (m0 + mt * 16 + a_row) * GROWB
                                  + ks * 32 + a_kof;
                    ldsm_x4(ahi[mt], ar);
                    ldsm_x4(alo[mt], ar + SA_SZ);
                }
                #pragma unroll
                for (int np = 0; np < 4; np++) {
                    uint32_t br = sb + SB_OFF
                                  + (n0 + np * 16 + b_row) * GROWB
                                  + ks * 32 + b_kof;
                    uint32_t bhi[4], blo[4];
                    ldsm_x4(bhi, br);
                    ldsm_x4(blo, br + SB_SZ);
                    #pragma unroll
                    for (int h = 0; h < 2; h++)
                        #pragma unroll
                        for (int mt = 0; mt < 2; mt++)
                            mma16816(acc[mt][np * 2 + h], ahi[mt],
                                     bhi[2 * h], bhi[2 * h + 1]);
                    #pragma unroll
                    for (int h = 0; h < 2; h++)
                        #pragma unroll
                        for (int mt = 0; mt < 2; mt++)
                            mma16816(acc[mt][np * 2 + h], ahi[mt],
                                     blo[2 * h], blo[2 * h + 1]);
                    #pragma unroll
                    for (int h = 0; h < 2; h++)
                        #pragma unroll
                        for (int mt = 0; mt < 2; mt++)
                            mma16816(acc[mt][np * 2 + h], alo[mt],
                                     bhi[2 * h], bhi[2 * h + 1]);
                }
            }
            if (it + 2 < 32) load_stage(it + 2, (it + 2) % 3);
        }

        #pragma unroll
        for (int mt = 0; mt < 2; mt++) {
            #pragma unroll
            for (int nt = 0; nt < 8; nt++) {
                int n = bn * 128 + n0 + nt * 8 + tig * 2;
                float bx = v_b[n], by = v_b[n + 1];
                #pragma unroll
                for (int half = 0; half < 2; half++) {
                    int m = bm * 256 + m0 + mt * 16 + gid + half * 8;
                    float vx = acc[mt][nt][half * 2 + 0] + bx;
                    float vy = acc[mt][nt][half * 2 + 1] + by;
                    int t = m >> 2, b = m & 3;
                    int h = n >> 6, d = n & 63;
                    int u = t * 16 + h;
                    int x = b * 16 + u / 1025;
                    int y = u % 1025;
                    size_t idx = ((size_t)x * SLEN + y) * HD + d;
                    uint32_t hi, lo;
                    split2h(vx, vy, hi, lo);
                    *reinterpret_cast<uint32_t*>(&g_Vh16[idx]) = hi;
                    *reinterpret_cast<uint32_t*>(&g_Vl16[idx]) = lo;
                }
            }
        }
    } else {
        // ---------------- light path: Q / K projection (hi-only)
        const int bl = bn - 8;
        const int sel = bl >> 3;                 // 0=Q, 1=K
        const char* gB0 = (const char*)(g_Whi[sel]
                          + (size_t)((bl & 7) * 128) * 1024);

        auto load_l = [&](int it, int buf) {
            uint32_t sb = smem_u + buf * LSTAGE;
            const int kb = it * 64;
            #pragma unroll
            for (int i = 0; i < 3; i++) {
                int idx = tid + i * 512;
                if (idx < 1024) {
                    int row = idx >> 2, c = idx & 3;
                    CP16(sb + row * GROWB + c * 16,
                         gA0 + (size_t)row * 2048 + kb + c * 16);
                } else {
                    int i2 = idx - 1024;
                    int row = i2 >> 2, c = i2 & 3;
                    CP16(sb + LSB_OFF + row * GROWB + c * 16,
                         gB0 + (size_t)row * 2048 + kb + c * 16);
                }
            }
            CPCOMMIT();
        };

        float acc[2][8][4] = {};
        load_l(0, 0);
        load_l(1, 1);

        for (int it = 0; it < 32; it++) {
            int buf = it % 3;
            if (it < 31) { CPWAIT1(); } else { CPWAIT0(); }
            __syncthreads();
            uint32_t sb = smem_u + buf * LSTAGE;
            #pragma unroll
            for (int ks = 0; ks < 2; ks++) {
                uint32_t ahi[2][4];
                #pragma unroll
                for (int mt = 0; mt < 2; mt++)
                    ldsm_x4(ahi[mt], sb + (m0 + mt * 16 + a_row) * GROWB
                                     + ks * 32 + a_kof);
                #pragma unroll
                for (int np = 0; np < 4; np++) {
                    uint32_t bhi[4];
                    ldsm_x4(bhi, sb + LSB_OFF
                                 + (n0 + np * 16 + b_row) * GROWB
                                 + ks * 32 + b_kof);
                    #pragma unroll
                    for (int h = 0; h < 2; h++)
                        #pragma unroll
                        for (int mt = 0; mt < 2; mt++)
                            mma16816(acc[mt][np * 2 + h], ahi[mt],
                                     bhi[2 * h], bhi[2 * h + 1]);
                }
            }
            if (it + 2 < 32) load_l(it + 2, (it + 2) % 3);
        }

        const float* bias = (sel == 0) ? q_b : k_b;
        #pragma unroll
        for (int mt = 0; mt < 2; mt++) {
            #pragma unroll
            for (int nt = 0; nt < 8; nt++) {
                int n = (bl & 7) * 128 + n0 + nt * 8 + tig * 2;
                float bx = bias[n], by = bias[n + 1];
                #pragma unroll
                for (int half = 0; half < 2; half++) {
                    int m = bm * 256 + m0 + mt * 16 + gid + half * 8;
                    float vx = acc[mt][nt][half * 2 + 0] + bx;
                    float vy = acc[mt][nt][half * 2 + 1] + by;
                    int t = m >> 2, b = m & 3;
                    int h = n >> 6, d = n & 63;
                    if (sel == 0) {
                        int x = b * 16 + (t >> 6);
                        int y = ((t & 63) << 4) | h;
                        size_t idx = ((size_t)x * T_ + y) * HD + d;
                        *reinterpret_cast<uint32_t*>(&g_Qh[idx]) =
                            pack2(vx * QSCALE2, vy * QSCALE2);
                    } else {
                        int u = t * 16 + h;
                        int x = b * 16 + u / 1025;
                        int y = u % 1025;
                        size_t idx = ((size_t)x * SLEN + y) * HD + d;
                        *reinterpret_cast<uint32_t*>(&g_Kh[idx]) =
                            pack2(vx, vy);
                    }
                }
            }
        }
    }
}

// ---------------------------------------------------------------- out proj GEMM
__global__ __launch_bounds__(512, 1)
void gemm_out(const __nv_bfloat16* __restrict__ Ahi,
              const __nv_bfloat16* __restrict__ Alo,
              const __nv_bfloat16* __restrict__ Bhi,
              const __nv_bfloat16* __restrict__ Blo,
              const float* __restrict__ bias,
              float* __restrict__ Cout)
{
    extern __shared__ __align__(16) char sm_[];
    const int tid = threadIdx.x, lane = tid & 31, w = tid >> 5;
    const int bn = blockIdx.x, bm = blockIdx.y;
    const uint32_t smem_u = cvta_smem(sm_);

    const int wm = w >> 1, wn = w & 1;
    const int m0 = wm * 32, n0 = wn * 64;
    const int gid = lane >> 2, tig = lane & 3;
    const int mat = lane >> 3, rowin = lane & 7;
    const int a_row = rowin + (mat & 1) * 8;
    const int a_kof = (mat >> 1) * 16;
    const int b_row = rowin + (mat >> 1) * 8;
    const int b_kof = (mat & 1) * 16;

    const char* gA0 = (const char*)(Ahi + (size_t)(bm * 256) * 1024);
    const char* gA1 = (const char*)(Alo + (size_t)(bm * 256) * 1024);
    const char* gB0 = (const char*)(Bhi + (size_t)(bn * 128) * 1024);
    const char* gB1 = (const char*)(Blo + (size_t)(bn * 128) * 1024);

    auto load_stage = [&](int it, int buf) {
        uint32_t sb = smem_u + buf * STAGE;
        const int kb = it * 64;
        #pragma unroll
        for (int i = 0; i < 6; i++) {
            int idx = tid + i * 512;
            if (idx < 2048) {
                int tile = idx >> 10, row = (idx >> 2) & 255, c = idx & 3;
                const char* g = (tile ? gA1 : gA0)
                                + (size_t)row * 2048 + kb + c * 16;
                CP16(sb + tile * SA_SZ + row * GROWB + c * 16, g);
            } else {
                int i2 = idx - 2048;
                int tile = i2 >> 9, row = (i2 >> 2) & 127, c = i2 & 3;
                const char* g = (tile ? gB1 : gB0)
                                + (size_t)row * 2048 + kb + c * 16;
                CP16(sb + SB_OFF + tile * SB_SZ + row * GROWB + c * 16, g);
            }
        }
        CPCOMMIT();
    };

    float acc[2][8][4] = {};
    load_stage(0, 0);
    load_stage(1, 1);

    for (int it = 0; it < 32; it++) {
        int buf = it % 3;
        if (it < 31) { CPWAIT1(); } else { CPWAIT0(); }
        __syncthreads();
        uint32_t sb = smem_u + buf * STAGE;
        #pragma unroll
        for (int ks = 0; ks < 2; ks++) {
            uint32_t ahi[2][4], alo[2][4];
            #pragma unroll
            for (int mt = 0; mt < 2; mt++) {
                uint32_t ar = sb + (m0 + mt * 16 + a_row) * GROWB
                              + ks * 32 + a_kof;
                ldsm_x4(ahi[mt], ar);
                ldsm_x4(alo[mt], ar + SA_SZ);
            }
            #pragma unroll
            for (int np = 0; np < 4; np++) {
                uint32_t br = sb + SB_OFF + (n0 + np * 16 + b_row) * GROWB
                              + ks * 32 + b_kof;
                uint32_t bhi[4], blo[4];
                ldsm_x4(bhi, br);
                ldsm_x4(blo, br + SB_SZ);
                #pragma unroll
                for (int h = 0; h < 2; h++)
                    #pragma unroll
                    for (int mt = 0; mt < 2; mt++)
                        mma16816(acc[mt][np * 2 + h], ahi[mt],
                                 bhi[2 * h], bhi[2 * h + 1]);
                #pragma unroll
                for (int h = 0; h < 2; h++)
                    #pragma unroll
                    for (int mt = 0; mt < 2; mt++)
                        mma16816(acc[mt][np * 2 + h], ahi[mt],
                                 blo[2 * h], blo[2 * h + 1]);
                #pragma unroll
                for (int h = 0; h < 2; h++)
                    #pragma unroll
                    for (int mt = 0; mt < 2; mt++)
                        mma16816(acc[mt][np * 2 + h], alo[mt],
                                 bhi[2 * h], bhi[2 * h + 1]);
            }
        }
        if (it + 2 < 32) load_stage(it + 2, (it + 2) % 3);
    }

    #pragma unroll
    for (int mt = 0; mt < 2; mt++) {
        #pragma unroll
        for (int nt = 0; nt < 8; nt++) {
            int n = bn * 128 + n0 + nt * 8 + tig * 2;
            float bx = bias[n], by = bias[n + 1];
            #pragma unroll
            for (int half = 0; half < 2; half++) {
                int m = bm * 256 + m0 + mt * 16 + gid + half * 8;
                *reinterpret_cast<float2*>(&Cout[(size_t)m * E_ + n]) =
                    make_float2(acc[mt][nt][half * 2 + 0] + bx,
                                acc[mt][nt][half * 2 + 1] + by);
            }
        }
    }
}

// ---------------------------------------------------------------- attention
// 128 q-rows per CTA, 4 warps x 32 q-rows, 128 threads, 2 CTAs/SM.
// QK^T: bf16 1-term. PV: fp16, P single + V hi/lo (2 terms).
// Chunks 0-15 full & unmasked; chunk 16 (1 valid key) specialized tail.
__global__ __launch_bounds__(128, 2)
void attn_mma(const float* __restrict__ grep_w,
              const float* __restrict__ grep_b,
              const float* __restrict__ grep_a)
{
    extern __shared__ __align__(16) char asmm[];
    const uint32_t smem_u = cvta_smem(asmm);
    const int tid = threadIdx.x, lane = tid & 31, w = tid >> 5;
    const int gid = lane >> 2, tig = lane & 3;
    const int mat = lane >> 3, rowin = lane & 7;
    const int x = blockIdx.y, t0 = blockIdx.x * 128;
    const int hx = x & 15, bx = x >> 4;

    float* gate_s = reinterpret_cast<float*>(asmm + A_GT);   // [128]
    float* gws_s  = gate_s + 128;                             // [64]
    float* misc_s = gws_s + 64;                               // [2]
    float* pb_s   = reinterpret_cast<float*>(asmm + A_PB);    // [2048]

    if (tid < 64) {
        float s = 0.f;
        #pragma unroll
        for (int j = 0; j < 8; j++) s += grep_w[tid * 8 + j];
        gws_s[tid] = s;
    }
    if (tid == 64) {
        float s = 0.f;
        #pragma unroll
        for (int j = 0; j < 8; j++) s += grep_b[j];
        misc_s[0] = s;
    }
    if (tid == 65) misc_s[1] = grep_a[hx];

    // Q tile (128 rows x 128B) + pb row (8KB)
    {
        const char* srcH = (const char*)g_Qh + ((size_t)x * T_ + t0) * HD * 2;
        #pragma unroll
        for (int i = 0; i < 8; i++) {
            int idx = tid + i * 128;
            int row = idx >> 3, c = idx & 7;
            CP16(smem_u + row * AROW + c * 16,
                 srcH + (size_t)row * 128 + c * 16);
        }
        const char* pbg = (const char*)(g_pb + (size_t)hx * 2048);
        #pragma unroll
        for (int i = 0; i < 4; i++) {
            int idx = tid + i * 128;
            CP16(smem_u + A_PB + idx * 16, pbg + idx * 16);
        }
        CPCOMMIT();
    }

    const char* pKh = (const char*)g_Kh + (size_t)x * SLEN * HD * 2;
    const char* pVh = (const char*)g_Vh16 + (size_t)x * SLEN * HD * 2;
    const char* pVl = (const char*)g_Vl16 + (size_t)x * SLEN * HD * 2;

    auto load_kv = [&](int ch, int buf) {
        int s0 = ch * 64;
        #pragma unroll
        for (int i = 0; i < 12; i++) {
            int idx = tid + i * 128;
            int tile = idx >> 9, row = (idx >> 3) & 63, c = idx & 7;
            const char* p = (tile == 0) ? pKh : (tile == 1) ? pVh : pVl;
            CP16(smem_u + A_ST + buf * A_STB + tile * ATILE
                 + row * AROW + c * 16,
                 p + (size_t)(s0 + row) * 128 + c * 16);
        }
        CPCOMMIT();
    };

    load_kv(0, 0);

    CPWAIT1();
    __syncthreads();
    {
        const __nv_bfloat16* qr =
            reinterpret_cast<const __nv_bfloat16*>(asmm + tid * AROW);
        float s = 0.f;
        #pragma unroll
        for (int d2 = 0; d2 < 64; d2++)
            s += __bfloat162float(qr[d2]) * gws_s[d2];
        gate_s[tid] = misc_s[1] /
                      (1.f + __expf(-(s * GATE_SC + misc_s[0])));
    }

    float l[2][2] = {};
    float o[2][8][4] = {};
    uint32_t qh[4][2][4];
    const int tgm0 = t0 + w * 32 + gid;
    float g0[2], g1[2];

    // ---------------- main loop: chunks 0..15 (all full, unmasked)
    for (int ch = 0; ch < 16; ch++) {
        int buf = ch & 1;
        load_kv(ch + 1, buf ^ 1);
        CPWAIT1();
        __syncthreads();

        if (ch == 0) {
            #pragma unroll
            for (int ks = 0; ks < 4; ks++)
                #pragma unroll
                for (int mt = 0; mt < 2; mt++)
                    ldsm_x4(qh[ks][mt], smem_u
                            + (w * 32 + mt * 16 + rowin + (mat & 1) * 8) * AROW
                            + ks * 32 + (mat >> 1) * 16);
            #pragma unroll
            for (int mt = 0; mt < 2; mt++) {
                g0[mt] = gate_s[w * 32 + mt * 16 + gid];
                g1[mt] = gate_s[w * 32 + mt * 16 + gid + 8];
            }
        }

        const uint32_t kb = smem_u + A_ST + buf * A_STB;

        // S = Q K^T
        float s_acc[2][8][4] = {};
        #pragma unroll
        for (int ks = 0; ks < 4; ks++) {
            #pragma unroll
            for (int np = 0; np < 4; np++) {
                uint32_t khf[4];
                ldsm_x4(khf, kb + (np * 16 + rowin + (mat >> 1) * 8) * AROW
                             + ks * 32 + (mat & 1) * 16);
                #pragma unroll
                for (int h2 = 0; h2 < 2; h2++)
                    #pragma unroll
                    for (int mt = 0; mt < 2; mt++)
                        mma16816(s_acc[mt][np * 2 + h2], qh[ks][mt],
                                 khf[2 * h2], khf[2 * h2 + 1]);
            }
        }

        // gated pos-bias + ex2
        int s0 = ch * 64;
        #pragma unroll
        for (int mt = 0; mt < 2; mt++) {
            const int base = s0 + tig * 2 + 1023 - (tgm0 + mt * 16);
            #pragma unroll
            for (int nt = 0; nt < 8; nt++) {
                float p0 = ex2f(s_acc[mt][nt][0] + g0[mt] * pb_s[base + nt * 8]);
                float p1 = ex2f(s_acc[mt][nt][1] + g0[mt] * pb_s[base + nt * 8 + 1]);
                float p2 = ex2f(s_acc[mt][nt][2] + g1[mt] * pb_s[base + nt * 8 - 8]);
                float p3 = ex2f(s_acc[mt][nt][3] + g1[mt] * pb_s[base + nt * 8 - 7]);
                s_acc[mt][nt][0] = p0; s_acc[mt][nt][1] = p1;
                s_acc[mt][nt][2] = p2; s_acc[mt][nt][3] = p3;
                l[mt][0] += p0 + p1; l[mt][1] += p2 + p3;
            }
        }

        // O += P V (fp16: P single, V hi/lo)
        const uint32_t vbh = kb + ATILE;
        const uint32_t vbl = kb + 2 * ATILE;
        #pragma unroll
        for (int ks = 0; ks < 4; ks++) {
            uint32_t ap[2][4];
            #pragma unroll
            for (int mt = 0; mt < 2; mt++)
                #pragma unroll
                for (int q = 0; q < 4; q++) {
                    int nt = 2 * ks + (q >> 1);
                    ap[mt][q] = pack2h(s_acc[mt][nt][(q & 1) * 2],
                                       s_acc[mt][nt][(q & 1) * 2 + 1]);
                }
            #pragma unroll
            for (int np = 0; np < 4; np++) {
                uint32_t va_off = (ks * 16 + rowin + (mat & 1) * 8) * AROW
                                  + (np * 16 + (mat >> 1) * 8) * 2;
                uint32_t vhf[4], vlf[4];
                ldsm_x4_t(vhf, vbh + va_off);
                ldsm_x4_t(vlf, vbl + va_off);
                #pragma unroll
                for (int mt = 0; mt < 2; mt++) {
                    #pragma unroll
                    for (int h2 = 0; h2 < 2; h2++)
                        mma16816h(o[mt][np * 2 + h2], ap[mt],
                                  vhf[2 * h2], vhf[2 * h2 + 1]);
                    #pragma unroll
                    for (int h2 = 0; h2 < 2; h2++)
                        mma16816h(o[mt][np * 2 + h2], ap[mt],
                                  vlf[2 * h2], vlf[2 * h2 + 1]);
                }
            }
        }
        __syncthreads();
    }

    // ---------------- tail: chunk 16 — only key 1024 is valid
    {
        CPWAIT0();
        __syncthreads();
        const uint32_t kb = smem_u + A_ST + 0 * A_STB;   // buf = 16 & 1 = 0

        // S for np=0 only (keys 1024..1039)
        float s16[2][2][4] = {};
        #pragma unroll
        for (int ks = 0; ks < 4; ks++) {
            uint32_t khf[4];
            ldsm_x4(khf, kb + (rowin + (mat >> 1) * 8) * AROW
                         + ks * 32 + (mat & 1) * 16);
            #pragma unroll
            for (int h2 = 0; h2 < 2; h2++)
                #pragma unroll
                for (int mt = 0; mt < 2; mt++)
                    mma16816(s16[mt][h2], qh[ks][mt],
                             khf[2 * h2], khf[2 * h2 + 1]);
        }
        // mask/exp: valid only when key == 1024 (nt=0, tig=0, even j)
        #pragma unroll
        for (int mt = 0; mt < 2; mt++) {
            #pragma unroll
            for (int j = 0; j < 4; j += 2) {
                float p = 0.f;
                if (tig == 0) {
                    int tg = tgm0 + mt * 16 + (j >> 1) * 8;
                    float g = (j >> 1) ? g1[mt] : g0[mt];
                    p = ex2f(s16[mt][0][j] + g * pb_s[2047 - tg]);
                }
                s16[mt][0][j] = p;
                if (j < 2) l[mt][0] += p; else l[mt][1] += p;
            }
            s16[mt][0][1] = 0.f; s16[mt][0][3] = 0.f;
            s16[mt][1][0] = 0.f; s16[mt][1][1] = 0.f;
            s16[mt][1][2] = 0.f; s16[mt][1][3] = 0.f;
        }
        // PV: ks=0 only
        const uint32_t vbh = kb + ATILE;
        const uint32_t vbl = kb + 2 * ATILE;
        uint32_t ap[2][4];
        #pragma unroll
        for (int mt = 0; mt < 2; mt++)
            #pragma unroll
            for (int q = 0; q < 4; q++) {
                int nt = q >> 1;
                ap[mt][q] = pack2h(s16[mt][nt][(q & 1) * 2],
                                   s16[mt][nt][(q & 1) * 2 + 1]);
            }
        #pragma unroll
        for (int np = 0; np < 4; np++) {
            uint32_t va_off = (rowin + (mat & 1) * 8) * AROW
                              + (np * 16 + (mat >> 1) * 8) * 2;
            uint32_t vhf[4], vlf[4];
            ldsm_x4_t(vhf, vbh + va_off);
            ldsm_x4_t(vlf, vbl + va_off);
            #pragma unroll
            for (int mt = 0; mt < 2; mt++) {
                #pragma unroll
                for (int h2 = 0; h2 < 2; h2++)
                    mma16816h(o[mt][np * 2 + h2], ap[mt],
                              vhf[2 * h2], vhf[2 * h2 + 1]);
                #pragma unroll
                for (int h2 = 0; h2 < 2; h2++)
                    mma16816h(o[mt][np * 2 + h2], ap[mt],
                              vlf[2 * h2], vlf[2 * h2 + 1]);
            }
        }
    }

    // ---- deferred row-sum reductions + epilogue
    #pragma unroll
    for (int mt = 0; mt < 2; mt++) {
        l[mt][0] += __shfl_xor_sync(0xffffffffu, l[mt][0], 1);
        l[mt][0] += __shfl_xor_sync(0xffffffffu, l[mt][0], 2);
        l[mt][1] += __shfl_xor_sync(0xffffffffu, l[mt][1], 1);
        l[mt][1] += __shfl_xor_sync(0xffffffffu, l[mt][1], 2);
        float inv0 = 1.0f / l[mt][0], inv1 = 1.0f / l[mt][1];
        int y0 = tgm0 + mt * 16, y1 = y0 + 8;
        #pragma unroll
        for (int nt = 0; nt < 8; nt++) {
            int col = hx * 64 + nt * 8 + tig * 2;
            uint32_t hi, lo;
            split2(o[mt][nt][0] * inv0, o[mt][nt][1] * inv0, hi, lo);
            size_t i0 = (size_t)(y0 * BZ + bx) * E_ + col;
            *reinterpret_cast<uint32_t*>(&g_Ahi[i0]) = hi;
            *reinterpret_cast<uint32_t*>(&g_Alo[i0]) = lo;
            split2(o[mt][nt][2] * inv1, o[mt][nt][3] * inv1, hi, lo);
            size_t i1 = (size_t)(y1 * BZ + bx) * E_ + col;
            *reinterpret_cast<uint32_t*>(&g_Ahi[i1]) = hi;
            *reinterpret_cast<uint32_t*>(&g_Alo[i1]) = lo;
        }
    }
}

// ---------------------------------------------------------------- host side
extern "C" void kernel_launch(void* const* d_in, const int* in_sizes, int n_in,
                              void* d_out, int out_size)
{
    (void)in_sizes; (void)n_in; (void)out_size;
    const float* query   = (const float*)d_in[0];
    const float* q_w     = (const float*)d_in[1];
    const float* q_b     = (const float*)d_in[2];
    const float* k_w     = (const float*)d_in[3];
    const float* k_b     = (const float*)d_in[4];
    const float* v_w     = (const float*)d_in[5];
    const float* v_b     = (const float*)d_in[6];
    const float* out_w   = (const float*)d_in[7];
    const float* out_b   = (const float*)d_in[8];
    const float* rel_emb = (const float*)d_in[9];
    const float* grep_w  = (const float*)d_in[10];
    const float* grep_b  = (const float*)d_in[11];
    const float* grep_a  = (const float*)d_in[12];
    const float* bias_k  = (const float*)d_in[13];
    const float* bias_v  = (const float*)d_in[14];
    float* out = (float*)d_out;

    void *pAhi, *pAlo, *pWhi, *pWlo;
    cudaGetSymbolAddress(&pAhi, g_Ahi);
    cudaGetSymbolAddress(&pAlo, g_Alo);
    cudaGetSymbolAddress(&pWhi, g_Whi);
    cudaGetSymbolAddress(&pWlo, g_Wlo);

    __nv_bfloat16* Ahi = (__nv_bfloat16*)pAhi;
    __nv_bfloat16* Alo = (__nv_bfloat16*)pAlo;
    const size_t wsz = (size_t)E_ * E_;
    __nv_bfloat16* Whi = (__nv_bfloat16*)pWhi;
    __nv_bfloat16* Wlo = (__nv_bfloat16*)pWlo;

    cudaFuncSetAttribute((const void*)gemm_qkv,
        cudaFuncAttributeMaxDynamicSharedMemorySize, GEMM_SMEM);
    cudaFuncSetAttribute((const void*)gemm_out,
        cudaFuncAttributeMaxDynamicSharedMemorySize, GEMM_SMEM);
    cudaFuncSetAttribute((const void*)attn_mma,
        cudaFuncAttributeMaxDynamicSharedMemorySize, ATTN_SMEM);

    prep_all<<<8208, 256>>>(query, q_w, k_w, v_w, out_w,
                            rel_emb, bias_k, bias_v);                    // 1
    gemm_qkv<<<dim3(24, 16), 512, GEMM_SMEM>>>(Ahi, Alo, q_b, k_b, v_b); // 2
    attn_mma<<<dim3(8, 64), 128, ATTN_SMEM>>>(grep_w, grep_b, grep_a);   // 3
    gemm_out<<<dim3(8, 16), 512, GEMM_SMEM>>>(                           // 4
        Ahi, Alo, Whi + 3 * wsz, Wlo + 3 * wsz, out_b, out);
}

// round 15
// speedup vs baseline: 1.5353x; 1.5353x over previous
#include <cuda_runtime.h>
#include <cuda_bf16.h>
#include <cuda_fp16.h>
#include <cstdint>

// ---------------------------------------------------------------- constants
#define T_   1024
#define BZ   4
#define E_   1024
#define NH   16
#define HD   64
#define BH   64
#define SLEN 1025
#define M_   4096
#define LOG2E 1.44269504f
#define QSCALE2 (0.00390625f * LOG2E)
#define GATE_SC (256.0f / LOG2E)

// GEMM tiling: CTA 256x128, 16 warps (8x2), warp 32x64, K-chunk 32 bf16
#define GROWB 80
#define SA_SZ (256 * GROWB)
#define SB_SZ (128 * GROWB)
#define SB_OFF (2 * SA_SZ)
#define STAGE (2 * SA_SZ + 2 * SB_SZ)   // 61440 (heavy)
#define LSB_OFF SA_SZ
#define LSTAGE (SA_SZ + SB_SZ)          // 30720 (light)
#define GEMM_SMEM (3 * STAGE)           // 184320

// attention smem: 128-row Q tile + gates + pb row + 2 stages x {KH, VH, VL}
#define AROW  144
#define ATILE (64 * AROW)               // 9216
#define A_GT  18432                     // gate[128], gws[64], misc[2]
#define A_PB  19456                     // pb row: 2048 f32 = 8192 B
#define A_ST  27648
#define A_STB (3 * ATILE)               // 27648
#define ATTN_SMEM (A_ST + 2 * A_STB)    // 82944

#define KVSZ ((size_t)BH * SLEN * HD + 8192)

// ---------------------------------------------------------------- scratch
__device__ __nv_bfloat16 g_Qh[(size_t)BH * T_ * HD];
__device__ __nv_bfloat16 g_Kh[KVSZ];
__device__ __half g_Vh16[KVSZ], g_Vl16[KVSZ];
__device__ float g_pb[(size_t)NH * 2048];

__device__ __nv_bfloat16 g_Ahi[(size_t)M_ * E_];
__device__ __nv_bfloat16 g_Alo[(size_t)M_ * E_];
__device__ __nv_bfloat16 g_Whi[4][(size_t)E_ * E_];
__device__ __nv_bfloat16 g_Wlo[4][(size_t)E_ * E_];

// ---------------------------------------------------------------- helpers
__device__ __forceinline__ uint32_t cvta_smem(const void* p) {
    uint32_t a;
    asm("{ .reg .u64 t; cvta.to.shared.u64 t, %1; cvt.u32.u64 %0, t; }"
        : "=r"(a) : "l"(p));
    return a;
}

#define CP16(dst, src) \
    asm volatile("cp.async.cg.shared.global [%0], [%1], 16;" \
        :: "r"(dst), "l"(src) : "memory")
#define CPCOMMIT() asm volatile("cp.async.commit_group;" ::: "memory")
#define CPWAIT1()  asm volatile("cp.async.wait_group 1;" ::: "memory")
#define CPWAIT0()  asm volatile("cp.async.wait_group 0;" ::: "memory")

__device__ __forceinline__ void ldsm_x4(uint32_t r[4], uint32_t addr) {
    asm volatile(
        "ldmatrix.sync.aligned.m8n8.x4.shared.b16 {%0,%1,%2,%3}, [%4];"
        : "=r"(r[0]), "=r"(r[1]), "=r"(r[2]), "=r"(r[3]) : "r"(addr));
}
__device__ __forceinline__ void ldsm_x4_t(uint32_t r[4], uint32_t addr) {
    asm volatile(
        "ldmatrix.sync.aligned.m8n8.x4.trans.shared.b16 {%0,%1,%2,%3}, [%4];"
        : "=r"(r[0]), "=r"(r[1]), "=r"(r[2]), "=r"(r[3]) : "r"(addr));
}

// bf16 mma
__device__ __forceinline__ void mma16816(float c[4], const uint32_t a[4],
                                         uint32_t b0, uint32_t b1) {
    asm volatile(
        "mma.sync.aligned.m16n8k16.row.col.f32.bf16.bf16.f32 "
        "{%0,%1,%2,%3}, {%4,%5,%6,%7}, {%8,%9}, {%0,%1,%2,%3};"
        : "+f"(c[0]), "+f"(c[1]), "+f"(c[2]), "+f"(c[3])
        : "r"(a[0]), "r"(a[1]), "r"(a[2]), "r"(a[3]), "r"(b0), "r"(b1));
}
// fp16 mma
__device__ __forceinline__ void mma16816h(float c[4], const uint32_t a[4],
                                          uint32_t b0, uint32_t b1) {
    asm volatile(
        "mma.sync.aligned.m16n8k16.row.col.f32.f16.f16.f32 "
        "{%0,%1,%2,%3}, {%4,%5,%6,%7}, {%8,%9}, {%0,%1,%2,%3};"
        : "+f"(c[0]), "+f"(c[1]), "+f"(c[2]), "+f"(c[3])
        : "r"(a[0]), "r"(a[1]), "r"(a[2]), "r"(a[3]), "r"(b0), "r"(b1));
}

__device__ __forceinline__ float ex2f(float x) {
    float y;
    asm("ex2.approx.f32 %0, %1;" : "=f"(y) : "f"(x));
    return y;
}

__device__ __forceinline__ uint32_t pack2(float x, float y) {
    __nv_bfloat162 t = __float22bfloat162_rn(make_float2(x, y));
    return *reinterpret_cast<uint32_t*>(&t);
}
__device__ __forceinline__ uint32_t pack2h(float x, float y) {
    __half2 t = __float22half2_rn(make_float2(x, y));
    return *reinterpret_cast<uint32_t*>(&t);
}

// packed bf16x2 split
__device__ __forceinline__ void split2(float x, float y,
                                       uint32_t& hi, uint32_t& lo) {
    __nv_bfloat162 h2 = __float22bfloat162_rn(make_float2(x, y));
    float2 hf = __bfloat1622float2(h2);
    __nv_bfloat162 l2 = __float22bfloat162_rn(make_float2(x - hf.x, y - hf.y));
    hi = *reinterpret_cast<uint32_t*>(&h2);
    lo = *reinterpret_cast<uint32_t*>(&l2);
}
// packed fp16x2 split
__device__ __forceinline__ void split2h(float x, float y,
                                        uint32_t& hi, uint32_t& lo) {
    __half2 h2 = __float22half2_rn(make_float2(x, y));
    float2 hf = __half22float2(h2);
    __half2 l2 = __float22half2_rn(make_float2(x - hf.x, y - hf.y));
    hi = *reinterpret_cast<uint32_t*>(&h2);
    lo = *reinterpret_cast<uint32_t*>(&l2);
}

// ---------------------------------------------------------------- prep_all
__global__ __launch_bounds__(256)
void prep_all(const float* __restrict__ query,
              const float* __restrict__ w0, const float* __restrict__ w1,
              const float* __restrict__ w2, const float* __restrict__ w3,
              const float* __restrict__ rel_emb,
              const float* __restrict__ bias_k,
              const float* __restrict__ bias_v)
{
    __shared__ float tile[32][33];
    int bid = blockIdx.x;
    int tid = threadIdx.x;

    if (bid < 4096) {
        int i = bid * 256 + tid;
        float4 v = reinterpret_cast<const float4*>(query)[i];
        uint32_t h0, l0, h1, l1;
        split2(v.x, v.y, h0, l0);
        split2(v.z, v.w, h1, l1);
        uint32_t* hp = reinterpret_cast<uint32_t*>(g_Ahi);
        uint32_t* lp = reinterpret_cast<uint32_t*>(g_Alo);
        hp[2 * i] = h0; hp[2 * i + 1] = h1;
        lp[2 * i] = l0; lp[2 * i + 1] = l1;
    } else if (bid < 8192) {
        int b2 = bid - 4096;
        int z = b2 >> 10;
        int rem = b2 & 1023;
        int bx = (rem & 31) * 32, by = (rem >> 5) * 32;
        int tx = tid & 31, ty = tid >> 5;
        const float* W = (z == 0) ? w0 : (z == 1) ? w1 : (z == 2) ? w2 : w3;
        __nv_bfloat16* hi = g_Whi[z];
        __nv_bfloat16* lo = g_Wlo[z];
        #pragma unroll
        for (int r = 0; r < 4; r++)
            tile[ty + r * 8][tx] = W[(size_t)(by + ty + r * 8) * E_ + bx + tx];
        __syncthreads();
        #pragma unroll
        for (int r = 0; r < 4; r++) {
            int n = bx + ty + r * 8, k = by + tx;
            float v = tile[tx][ty + r * 8];
            __nv_bfloat16 h = __float2bfloat16(v);
            hi[(size_t)n * E_ + k] = h;
            lo[(size_t)n * E_ + k] = __float2bfloat16(v - __bfloat162float(h));
        }
    } else {
        int i = (bid - 8192) * 256 + tid;
        if (i < 2048) {
            int rel = i - 1023;
            int bkt = rel > 0 ? 16 : 0;
            int a = rel < 0 ? -rel : rel;
            int bu;
            if (a < 8) {
                bu = a;
            } else {
                float lf = logf((float)a * 0.125f + 1e-6f)
                           * (8.0f / 2.772588722239781f);
                int large = 8 + (int)lf;
                bu = large < 15 ? large : 15;
            }
            int bucket = bkt + bu;
            #pragma unroll
            for (int h = 0; h < NH; h++)
                g_pb[h * 2048 + i] = rel_emb[bucket * NH + h] * LOG2E;
        }
        int b = i >> 10, h = (i >> 6) & 15, d = i & 63;
        int x = b * 16 + 15;
        int y = 1009 + h;
        size_t idx = ((size_t)x * SLEN + y) * HD + d;
        float kv = bias_k[h * HD + d];
        float vv = bias_v[h * HD + d];
        __half vh = __float2half(vv);
        g_Kh[idx] = __float2bfloat16(kv);
        g_Vh16[idx] = vh;
        g_Vl16[idx] = __float2half(vv - __half2float(vh));
    }
}

// ---------------------------------------------------------------- fused QKV GEMM
// grid (24, 16): bn 0-7 -> V proj (heavy, 3-term bf16 split, fp16 output)
//                bn 8-15 -> Q proj (light), bn 16-23 -> K proj (light)
__global__ __launch_bounds__(512, 1)
void gemm_qkv(const __nv_bfloat16* __restrict__ Ahi,
              const __nv_bfloat16* __restrict__ Alo,
              const float* __restrict__ q_b,
              const float* __restrict__ k_b,
              const float* __restrict__ v_b)
{
    extern __shared__ __align__(16) char sm_[];
    const int tid = threadIdx.x, lane = tid & 31, w = tid >> 5;
    const int bn = blockIdx.x, bm = blockIdx.y;
    const uint32_t smem_u = cvta_smem(sm_);

    const int wm = w >> 1, wn = w & 1;
    const int m0 = wm * 32, n0 = wn * 64;
    const int gid = lane >> 2, tig = lane & 3;
    const int mat = lane >> 3, rowin = lane & 7;
    const int a_row = rowin + (mat & 1) * 8;
    const int a_kof = (mat >> 1) * 16;
    const int b_row = rowin + (mat >> 1) * 8;
    const int b_kof = (mat & 1) * 16;

    const char* gA0 = (const char*)(Ahi + (size_t)(bm * 256) * 1024);
    const char* gA1 = (const char*)(Alo + (size_t)(bm * 256) * 1024);

    if (bn < 8) {
        // ---------------- heavy path: V projection
        const char* gB0 = (const char*)(g_Whi[2] + (size_t)(bn * 128) * 1024);
        const char* gB1 = (const char*)(g_Wlo[2] + (size_t)(bn * 128) * 1024);

        auto load_stage = [&](int it, int buf) {
            uint32_t sb = smem_u + buf * STAGE;
            const int kb = it * 64;
            #pragma unroll
            for (int i = 0; i < 6; i++) {
                int idx = tid + i * 512;
                if (idx < 2048) {
                    int tile = idx >> 10, row = (idx >> 2) & 255, c = idx & 3;
                    const char* g = (tile ? gA1 : gA0)
                                    + (size_t)row * 2048 + kb + c * 16;
                    CP16(sb + tile * SA_SZ + row * GROWB + c * 16, g);
                } else {
                    int i2 = idx - 2048;
                    int tile = i2 >> 9, row = (i2 >> 2) & 127, c = i2 & 3;
                    const char* g = (tile ? gB1 : gB0)
                                    + (size_t)row * 2048 + kb + c * 16;
                    CP16(sb + SB_OFF + tile * SB_SZ + row * GROWB + c * 16, g);
                }
            }
            CPCOMMIT();
        };

        float acc[2][8][4] = {};
        load_stage(0, 0);
        load_stage(1, 1);

        for (int it = 0; it < 32; it++) {
            int buf = it % 3;
            if (it < 31) { CPWAIT1(); } else { CPWAIT0(); }
            __syncthreads();
            uint32_t sb = smem_u + buf * STAGE;
            #pragma unroll
            for (int ks = 0; ks < 2; ks++) {
                uint32_t ahi[2][4], alo[2][4];
                #pragma unroll
                for (int mt = 0; mt < 2; mt++) {
                    uint32_t ar = sb + (m0 + mt * 16 + a_row) * GROWB
                                  + ks * 32 + a_kof;
                    ldsm_x4(ahi[mt], ar);
                    ldsm_x4(alo[mt], ar + SA_SZ);
                }
                #pragma unroll
                for (int np = 0; np < 4; np++) {
                    uint32_t br = sb + SB_OFF
                                  + (n0 + np * 16 + b_row) * GROWB
                                  + ks * 32 + b_kof;
                    uint32_t bhi[4], blo[4];
                    ldsm_x4(bhi, br);
                    ldsm_x4(blo, br + SB_SZ);
                    #pragma unroll
                    for (int h = 0; h < 2; h++)
                        #pragma unroll
                        for (int mt = 0; mt < 2; mt++)
                            mma16816(acc[mt][np * 2 + h], ahi[mt],
                                     bhi[2 * h], bhi[2 * h + 1]);
                    #pragma unroll
                    for (int h = 0; h < 2; h++)
                        #pragma unroll
                        for (int mt = 0; mt < 2; mt++)
                            mma16816(acc[mt][np * 2 + h], ahi[mt],
                                     blo[2 * h], blo[2 * h + 1]);
                    #pragma unroll
                    for (int h = 0; h < 2; h++)
                        #pragma unroll
                        for (int mt = 0; mt < 2; mt++)
                            mma16816(acc[mt][np * 2 + h], alo[mt],
                                     bhi[2 * h], bhi[2 * h + 1]);
                }
            }
            if (it + 2 < 32) load_stage(it + 2, (it + 2) % 3);
        }

        #pragma unroll
        for (int mt = 0; mt < 2; mt++) {
            #pragma unroll
            for (int nt = 0; nt < 8; nt++) {
                int n = bn * 128 + n0 + nt * 8 + tig * 2;
                float bx = v_b[n], by = v_b[n + 1];
                #pragma unroll
                for (int half = 0; half < 2; half++) {
                    int m = bm * 256 + m0 + mt * 16 + gid + half * 8;
                    float vx = acc[mt][nt][half * 2 + 0] + bx;
                    float vy = acc[mt][nt][half * 2 + 1] + by;
                    int t = m >> 2, b = m & 3;
                    int h = n >> 6, d = n & 63;
                    int u = t * 16 + h;
                    int x = b * 16 + u / 1025;
                    int y = u % 1025;
                    size_t idx = ((size_t)x * SLEN + y) * HD + d;
                    uint32_t hi, lo;
                    split2h(vx, vy, hi, lo);
                    *reinterpret_cast<uint32_t*>(&g_Vh16[idx]) = hi;
                    *reinterpret_cast<uint32_t*>(&g_Vl16[idx]) = lo;
                }
            }
        }
    } else {
        // ---------------- light path: Q / K projection (hi-only)
        const int bl = bn - 8;
        const int sel = bl >> 3;                 // 0=Q, 1=K
        const char* gB0 = (const char*)(g_Whi[sel]
                          + (size_t)((bl & 7) * 128) * 1024);

        auto load_l = [&](int it, int buf) {
            uint32_t sb = smem_u + buf * LSTAGE;
            const int kb = it * 64;
            #pragma unroll
            for (int i = 0; i < 3; i++) {
                int idx = tid + i * 512;
                if (idx < 1024) {
                    int row = idx >> 2, c = idx & 3;
                    CP16(sb + row * GROWB + c * 16,
                         gA0 + (size_t)row * 2048 + kb + c * 16);
                } else {
                    int i2 = idx - 1024;
                    int row = i2 >> 2, c = i2 & 3;
                    CP16(sb + LSB_OFF + row * GROWB + c * 16,
                         gB0 + (size_t)row * 2048 + kb + c * 16);
                }
            }
            CPCOMMIT();
        };

        float acc[2][8][4] = {};
        load_l(0, 0);
        load_l(1, 1);

        for (int it = 0; it < 32; it++) {
            int buf = it % 3;
            if (it < 31) { CPWAIT1(); } else { CPWAIT0(); }
            __syncthreads();
            uint32_t sb = smem_u + buf * LSTAGE;
            #pragma unroll
            for (int ks = 0; ks < 2; ks++) {
                uint32_t ahi[2][4];
                #pragma unroll
                for (int mt = 0; mt < 2; mt++)
                    ldsm_x4(ahi[mt], sb + (m0 + mt * 16 + a_row) * GROWB
                                     + ks * 32 + a_kof);
                #pragma unroll
                for (int np = 0; np < 4; np++) {
                    uint32_t bhi[4];
                    ldsm_x4(bhi, sb + LSB_OFF
                                 + (n0 + np * 16 + b_row) * GROWB
                                 + ks * 32 + b_kof);
                    #pragma unroll
                    for (int h = 0; h < 2; h++)
                        #pragma unroll
                        for (int mt = 0; mt < 2; mt++)
                            mma16816(acc[mt][np * 2 + h], ahi[mt],
                                     bhi[2 * h], bhi[2 * h + 1]);
                }
            }
            if (it + 2 < 32) load_l(it + 2, (it + 2) % 3);
        }

        const float* bias = (sel == 0) ? q_b : k_b;
        #pragma unroll
        for (int mt = 0; mt < 2; mt++) {
            #pragma unroll
            for (int nt = 0; nt < 8; nt++) {
                int n = (bl & 7) * 128 + n0 + nt * 8 + tig * 2;
                float bx = bias[n], by = bias[n + 1];
                #pragma unroll
                for (int half = 0; half < 2; half++) {
                    int m = bm * 256 + m0 + mt * 16 + gid + half * 8;
                    float vx = acc[mt][nt][half * 2 + 0] + bx;
                    float vy = acc[mt][nt][half * 2 + 1] + by;
                    int t = m >> 2, b = m & 3;
                    int h = n >> 6, d = n & 63;
                    if (sel == 0) {
                        int x = b * 16 + (t >> 6);
                        int y = ((t & 63) << 4) | h;
                        size_t idx = ((size_t)x * T_ + y) * HD + d;
                        *reinterpret_cast<uint32_t*>(&g_Qh[idx]) =
                            pack2(vx * QSCALE2, vy * QSCALE2);
                    } else {
                        int u = t * 16 + h;
                        int x = b * 16 + u / 1025;
                        int y = u % 1025;
                        size_t idx = ((size_t)x * SLEN + y) * HD + d;
                        *reinterpret_cast<uint32_t*>(&g_Kh[idx]) =
                            pack2(vx, vy);
                    }
                }
            }
        }
    }
}

// ---------------------------------------------------------------- out proj GEMM
__global__ __launch_bounds__(512, 1)
void gemm_out(const __nv_bfloat16* __restrict__ Ahi,
              const __nv_bfloat16* __restrict__ Alo,
              const __nv_bfloat16* __restrict__ Bhi,
              const __nv_bfloat16* __restrict__ Blo,
              const float* __restrict__ bias,
              float* __restrict__ Cout)
{
    extern __shared__ __align__(16) char sm_[];
    const int tid = threadIdx.x, lane = tid & 31, w = tid >> 5;
    const int bn = blockIdx.x, bm = blockIdx.y;
    const uint32_t smem_u = cvta_smem(sm_);

    const int wm = w >> 1, wn = w & 1;
    const int m0 = wm * 32, n0 = wn * 64;
    const int gid = lane >> 2, tig = lane & 3;
    const int mat = lane >> 3, rowin = lane & 7;
    const int a_row = rowin + (mat & 1) * 8;
    const int a_kof = (mat >> 1) * 16;
    const int b_row = rowin + (mat >> 1) * 8;
    const int b_kof = (mat & 1) * 16;

    const char* gA0 = (const char*)(Ahi + (size_t)(bm * 256) * 1024);
    const char* gA1 = (const char*)(Alo + (size_t)(bm * 256) * 1024);
    const char* gB0 = (const char*)(Bhi + (size_t)(bn * 128) * 1024);
    const char* gB1 = (const char*)(Blo + (size_t)(bn * 128) * 1024);

    auto load_stage = [&](int it, int buf) {
        uint32_t sb = smem_u + buf * STAGE;
        const int kb = it * 64;
        #pragma unroll
        for (int i = 0; i < 6; i++) {
            int idx = tid + i * 512;
            if (idx < 2048) {
                int tile = idx >> 10, row = (idx >> 2) & 255, c = idx & 3;
                const char* g = (tile ? gA1 : gA0)
                                + (size_t)row * 2048 + kb + c * 16;
                CP16(sb + tile * SA_SZ + row * GROWB + c * 16, g);
            } else {
                int i2 = idx - 2048;
                int tile = i2 >> 9, row = (i2 >> 2) & 127, c = i2 & 3;
                const char* g = (tile ? gB1 : gB0)
                                + (size_t)row * 2048 + kb + c * 16;
                CP16(sb + SB_OFF + tile * SB_SZ + row * GROWB + c * 16, g);
            }
        }
        CPCOMMIT();
    };

    float acc[2][8][4] = {};
    load_stage(0, 0);
    load_stage(1, 1);

    for (int it = 0; it < 32; it++) {
        int buf = it % 3;
        if (it < 31) { CPWAIT1(); } else { CPWAIT0(); }
        __syncthreads();
        uint32_t sb = smem_u + buf * STAGE;
        #pragma unroll
        for (int ks = 0; ks < 2; ks++) {
            uint32_t ahi[2][4], alo[2][4];
            #pragma unroll
            for (int mt = 0; mt < 2; mt++) {
                uint32_t ar = sb + (m0 + mt * 16 + a_row) * GROWB
                              + ks * 32 + a_kof;
                ldsm_x4(ahi[mt], ar);
                ldsm_x4(alo[mt], ar + SA_SZ);
            }
            #pragma unroll
            for (int np = 0; np < 4; np++) {
                uint32_t br = sb + SB_OFF + (n0 + np * 16 + b_row) * GROWB
                              + ks * 32 + b_kof;
                uint32_t bhi[4], blo[4];
                ldsm_x4(bhi, br);
                ldsm_x4(blo, br + SB_SZ);
                #pragma unroll
                for (int h = 0; h < 2; h++)
                    #pragma unroll
                    for (int mt = 0; mt < 2; mt++)
                        mma16816(acc[mt][np * 2 + h], ahi[mt],
                                 bhi[2 * h], bhi[2 * h + 1]);
                #pragma unroll
                for (int h = 0; h < 2; h++)
                    #pragma unroll
                    for (int mt = 0; mt < 2; mt++)
                        mma16816(acc[mt][np * 2 + h], ahi[mt],
                                 blo[2 * h], blo[2 * h + 1]);
                #pragma unroll
                for (int h = 0; h < 2; h++)
                    #pragma unroll
                    for (int mt = 0; mt < 2; mt++)
                        mma16816(acc[mt][np * 2 + h], alo[mt],
                                 bhi[2 * h], bhi[2 * h + 1]);
            }
        }
        if (it + 2 < 32) load_stage(it + 2, (it + 2) % 3);
    }

    #pragma unroll
    for (int mt = 0; mt < 2; mt++) {
        #pragma unroll
        for (int nt = 0; nt < 8; nt++) {
            int n = bn * 128 + n0 + nt * 8 + tig * 2;
            float bx = bias[n], by = bias[n + 1];
            #pragma unroll
            for (int half = 0; half < 2; half++) {
                int m = bm * 256 + m0 + mt * 16 + gid + half * 8;
                *reinterpret_cast<float2*>(&Cout[(size_t)m * E_ + n]) =
                    make_float2(acc[mt][nt][half * 2 + 0] + bx,
                                acc[mt][nt][half * 2 + 1] + by);
            }
        }
    }
}

// ---------------------------------------------------------------- attention
// 128 q-rows per CTA, 4 warps x 32 q-rows, 128 threads, 2 CTAs/SM.
// QK^T: bf16 1-term. PV: fp16, P single + V hi/lo (2 terms).
// Chunks 0-15 full & unmasked; chunk 16 (1 valid key) specialized tail.
__global__ __launch_bounds__(128, 2)
void attn_mma(const float* __restrict__ grep_w,
              const float* __restrict__ grep_b,
              const float* __restrict__ grep_a)
{
    extern __shared__ __align__(16) char asmm[];
    const uint32_t smem_u = cvta_smem(asmm);
    const int tid = threadIdx.x, lane = tid & 31, w = tid >> 5;
    const int gid = lane >> 2, tig = lane & 3;
    const int mat = lane >> 3, rowin = lane & 7;
    const int x = blockIdx.y, t0 = blockIdx.x * 128;
    const int hx = x & 15, bx = x >> 4;

    float* gate_s = reinterpret_cast<float*>(asmm + A_GT);   // [128]
    float* gws_s  = gate_s + 128;                             // [64]
    float* misc_s = gws_s + 64;                               // [2]
    float* pb_s   = reinterpret_cast<float*>(asmm + A_PB);    // [2048]

    if (tid < 64) {
        float s = 0.f;
        #pragma unroll
        for (int j = 0; j < 8; j++) s += grep_w[tid * 8 + j];
        gws_s[tid] = s;
    }
    if (tid == 64) {
        float s = 0.f;
        #pragma unroll
        for (int j = 0; j < 8; j++) s += grep_b[j];
        misc_s[0] = s;
    }
    if (tid == 65) misc_s[1] = grep_a[hx];

    // Q tile (128 rows x 128B) + pb row (8KB)
    {
        const char* srcH = (const char*)g_Qh + ((size_t)x * T_ + t0) * HD * 2;
        #pragma unroll
        for (int i = 0; i < 8; i++) {
            int idx = tid + i * 128;
            int row = idx >> 3, c = idx & 7;
            CP16(smem_u + row * AROW + c * 16,
                 srcH + (size_t)row * 128 + c * 16);
        }
        const char* pbg = (const char*)(g_pb + (size_t)hx * 2048);
        #pragma unroll
        for (int i = 0; i < 4; i++) {
            int idx = tid + i * 128;
            CP16(smem_u + A_PB + idx * 16, pbg + idx * 16);
        }
        CPCOMMIT();
    }

    const char* pKh = (const char*)g_Kh + (size_t)x * SLEN * HD * 2;
    const char* pVh = (const char*)g_Vh16 + (size_t)x * SLEN * HD * 2;
    const char* pVl = (const char*)g_Vl16 + (size_t)x * SLEN * HD * 2;

    auto load_kv = [&](int ch, int buf) {
        int s0 = ch * 64;
        #pragma unroll
        for (int i = 0; i < 12; i++) {
            int idx = tid + i * 128;
            int tile = idx >> 9, row = (idx >> 3) & 63, c = idx & 7;
            const char* p = (tile == 0) ? pKh : (tile == 1) ? pVh : pVl;
            CP16(smem_u + A_ST + buf * A_STB + tile * ATILE
                 + row * AROW + c * 16,
                 p + (size_t)(s0 + row) * 128 + c * 16);
        }
        CPCOMMIT();
    };

    load_kv(0, 0);

    CPWAIT1();
    __syncthreads();
    {
        const __nv_bfloat16* qr =
            reinterpret_cast<const __nv_bfloat16*>(asmm + tid * AROW);
        float s = 0.f;
        #pragma unroll
        for (int d2 = 0; d2 < 64; d2++)
            s += __bfloat162float(qr[d2]) * gws_s[d2];
        gate_s[tid] = misc_s[1] /
                      (1.f + __expf(-(s * GATE_SC + misc_s[0])));
    }

    float l[2][2] = {};
    float o[2][8][4] = {};
    uint32_t qh[4][2][4];
    const int tgm0 = t0 + w * 32 + gid;
    float g0[2], g1[2];

    // ---------------- main loop: chunks 0..15 (all full, unmasked)
    for (int ch = 0; ch < 16; ch++) {
        int buf = ch & 1;
        load_kv(ch + 1, buf ^ 1);
        CPWAIT1();
        __syncthreads();

        if (ch == 0) {
            #pragma unroll
            for (int ks = 0; ks < 4; ks++)
                #pragma unroll
                for (int mt = 0; mt < 2; mt++)
                    ldsm_x4(qh[ks][mt], smem_u
                            + (w * 32 + mt * 16 + rowin + (mat & 1) * 8) * AROW
                            + ks * 32 + (mat >> 1) * 16);
            #pragma unroll
            for (int mt = 0; mt < 2; mt++) {
                g0[mt] = gate_s[w * 32 + mt * 16 + gid];
                g1[mt] = gate_s[w * 32 + mt * 16 + gid + 8];
            }
        }

        const uint32_t kb = smem_u + A_ST + buf * A_STB;

        // S = Q K^T
        float s_acc[2][8][4] = {};
        #pragma unroll
        for (int ks = 0; ks < 4; ks++) {
            #pragma unroll
            for (int np = 0; np < 4; np++) {
                uint32_t khf[4];
                ldsm_x4(khf, kb + (np * 16 + rowin + (mat >> 1) * 8) * AROW
                             + ks * 32 + (mat & 1) * 16);
                #pragma unroll
                for (int h2 = 0; h2 < 2; h2++)
                    #pragma unroll
                    for (int mt = 0; mt < 2; mt++)
                        mma16816(s_acc[mt][np * 2 + h2], qh[ks][mt],
                                 khf[2 * h2], khf[2 * h2 + 1]);
            }
        }

        // gated pos-bias + ex2
        int s0 = ch * 64;
        #pragma unroll
        for (int mt = 0; mt < 2; mt++) {
            const int base = s0 + tig * 2 + 1023 - (tgm0 + mt * 16);
            #pragma unroll
            for (int nt = 0; nt < 8; nt++) {
                float p0 = ex2f(s_acc[mt][nt][0] + g0[mt] * pb_s[base + nt * 8]);
                float p1 = ex2f(s_acc[mt][nt][1] + g0[mt] * pb_s[base + nt * 8 + 1]);
                float p2 = ex2f(s_acc[mt][nt][2] + g1[mt] * pb_s[base + nt * 8 - 8]);
                float p3 = ex2f(s_acc[mt][nt][3] + g1[mt] * pb_s[base + nt * 8 - 7]);
                s_acc[mt][nt][0] = p0; s_acc[mt][nt][1] = p1;
                s_acc[mt][nt][2] = p2; s_acc[mt][nt][3] = p3;
                l[mt][0] += p0 + p1; l[mt][1] += p2 + p3;
            }
        }

        // O += P V (fp16: P single, V hi/lo)
        const uint32_t vbh = kb + ATILE;
        const uint32_t vbl = kb + 2 * ATILE;
        #pragma unroll
        for (int ks = 0; ks < 4; ks++) {
            uint32_t ap[2][4];
            #pragma unroll
            for (int mt = 0; mt < 2; mt++)
                #pragma unroll
                for (int q = 0; q < 4; q++) {
                    int nt = 2 * ks + (q >> 1);
                    ap[mt][q] = pack2h(s_acc[mt][nt][(q & 1) * 2],
                                       s_acc[mt][nt][(q & 1) * 2 + 1]);
                }
            #pragma unroll
            for (int np = 0; np < 4; np++) {
                uint32_t va_off = (ks * 16 + rowin + (mat & 1) * 8) * AROW
                                  + (np * 16 + (mat >> 1) * 8) * 2;
                uint32_t vhf[4], vlf[4];
                ldsm_x4_t(vhf, vbh + va_off);
                ldsm_x4_t(vlf, vbl + va_off);
                #pragma unroll
                for (int mt = 0; mt < 2; mt++) {
                    #pragma unroll
                    for (int h2 = 0; h2 < 2; h2++)
                        mma16816h(o[mt][np * 2 + h2], ap[mt],
                                  vhf[2 * h2], vhf[2 * h2 + 1]);
                    #pragma unroll
                    for (int h2 = 0; h2 < 2; h2++)
                        mma16816h(o[mt][np * 2 + h2], ap[mt],
                                  vlf[2 * h2], vlf[2 * h2 + 1]);
                }
            }
        }
        __syncthreads();
    }

    // ---------------- tail: chunk 16 — only key 1024 is valid
    {
        CPWAIT0();
        __syncthreads();
        const uint32_t kb = smem_u + A_ST + 0 * A_STB;   // buf = 16 & 1 = 0

        // S for np=0 only (keys 1024..1039)
        float s16[2][2][4] = {};
        #pragma unroll
        for (int ks = 0; ks < 4; ks++) {
            uint32_t khf[4];
            ldsm_x4(khf, kb + (rowin + (mat >> 1) * 8) * AROW
                         + ks * 32 + (mat & 1) * 16);
            #pragma unroll
            for (int h2 = 0; h2 < 2; h2++)
                #pragma unroll
                for (int mt = 0; mt < 2; mt++)
                    mma16816(s16[mt][h2], qh[ks][mt],
                             khf[2 * h2], khf[2 * h2 + 1]);
        }
        // mask/exp: valid only when key == 1024 (nt=0, tig=0, even j)
        #pragma unroll
        for (int mt = 0; mt < 2; mt++) {
            #pragma unroll
            for (int j = 0; j < 4; j += 2) {
                float p = 0.f;
                if (tig == 0) {
                    int tg = tgm0 + mt * 16 + (j >> 1) * 8;
                    float g = (j >> 1) ? g1[mt] : g0[mt];
                    p = ex2f(s16[mt][0][j] + g * pb_s[2047 - tg]);
                }
                s16[mt][0][j] = p;
                if (j < 2) l[mt][0] += p; else l[mt][1] += p;
            }
            s16[mt][0][1] = 0.f; s16[mt][0][3] = 0.f;
            s16[mt][1][0] = 0.f; s16[mt][1][1] = 0.f;
            s16[mt][1][2] = 0.f; s16[mt][1][3] = 0.f;
        }
        // PV: ks=0 only
        const uint32_t vbh = kb + ATILE;
        const uint32_t vbl = kb + 2 * ATILE;
        uint32_t ap[2][4];
        #pragma unroll
        for (int mt = 0; mt < 2; mt++)
            #pragma unroll
            for (int q = 0; q < 4; q++) {
                int nt = q >> 1;
                ap[mt][q] = pack2h(s16[mt][nt][(q & 1) * 2],
                                   s16[mt][nt][(q & 1) * 2 + 1]);
            }
        #pragma unroll
        for (int np = 0; np < 4; np++) {
            uint32_t va_off = (rowin + (mat & 1) * 8) * AROW
                              + (np * 16 + (mat >> 1) * 8) * 2;
            uint32_t vhf[4], vlf[4];
            ldsm_x4_t(vhf, vbh + va_off);
            ldsm_x4_t(vlf, vbl + va_off);
            #pragma unroll
            for (int mt = 0; mt < 2; mt++) {
                #pragma unroll
                for (int h2 = 0; h2 < 2; h2++)
                    mma16816h(o[mt][np * 2 + h2], ap[mt],
                              vhf[2 * h2], vhf[2 * h2 + 1]);
                #pragma unroll
                for (int h2 = 0; h2 < 2; h2++)
                    mma16816h(o[mt][np * 2 + h2], ap[mt],
                              vlf[2 * h2], vlf[2 * h2 + 1]);
            }
        }
    }

    // ---- deferred row-sum reductions + epilogue
    #pragma unroll
    for (int mt = 0; mt < 2; mt++) {
        l[mt][0] += __shfl_xor_sync(0xffffffffu, l[mt][0], 1);
        l[mt][0] += __shfl_xor_sync(0xffffffffu, l[mt][0], 2);
        l[mt][1] += __shfl_xor_sync(0xffffffffu, l[mt][1], 1);
        l[mt][1] += __shfl_xor_sync(0xffffffffu, l[mt][1], 2);
        float inv0 = 1.0f / l[mt][0], inv1 = 1.0f / l[mt][1];
        int y0 = tgm0 + mt * 16, y1 = y0 + 8;
        #pragma unroll
        for (int nt = 0; nt < 8; nt++) {
            int col = hx * 64 + nt * 8 + tig * 2;
            uint32_t hi, lo;
            split2(o[mt][nt][0] * inv0, o[mt][nt][1] * inv0, hi, lo);
            size_t i0 = (size_t)(y0 * BZ + bx) * E_ + col;
            *reinterpret_cast<uint32_t*>(&g_Ahi[i0]) = hi;
            *reinterpret_cast<uint32_t*>(&g_Alo[i0]) = lo;
            split2(o[mt][nt][2] * inv1, o[mt][nt][3] * inv1, hi, lo);
            size_t i1 = (size_t)(y1 * BZ + bx) * E_ + col;
            *reinterpret_cast<uint32_t*>(&g_Ahi[i1]) = hi;
            *reinterpret_cast<uint32_t*>(&g_Alo[i1]) = lo;
        }
    }
}

// ---------------------------------------------------------------- host side
extern "C" void kernel_launch(void* const* d_in, const int* in_sizes, int n_in,
                              void* d_out, int out_size)
{
    (void)in_sizes; (void)n_in; (void)out_size;
    const float* query   = (const float*)d_in[0];
    const float* q_w     = (const float*)d_in[1];
    const float* q_b     = (const float*)d_in[2];
    const float* k_w     = (const float*)d_in[3];
    const float* k_b     = (const float*)d_in[4];
    const float* v_w     = (const float*)d_in[5];
    const float* v_b     = (const float*)d_in[6];
    const float* out_w   = (const float*)d_in[7];
    const float* out_b   = (const float*)d_in[8];
    const float* rel_emb = (const float*)d_in[9];
    const float* grep_w  = (const float*)d_in[10];
    const float* grep_b  = (const float*)d_in[11];
    const float* grep_a  = (const float*)d_in[12];
    const float* bias_k  = (const float*)d_in[13];
    const float* bias_v  = (const float*)d_in[14];
    float* out = (float*)d_out;

    void *pAhi, *pAlo, *pWhi, *pWlo;
    cudaGetSymbolAddress(&pAhi, g_Ahi);
    cudaGetSymbolAddress(&pAlo, g_Alo);
    cudaGetSymbolAddress(&pWhi, g_Whi);
    cudaGetSymbolAddress(&pWlo, g_Wlo);

    __nv_bfloat16* Ahi = (__nv_bfloat16*)pAhi;
    __nv_bfloat16* Alo = (__nv_bfloat16*)pAlo;
    const size_t wsz = (size_t)E_ * E_;
    __nv_bfloat16* Whi = (__nv_bfloat16*)pWhi;
    __nv_bfloat16* Wlo = (__nv_bfloat16*)pWlo;

    cudaFuncSetAttribute((const void*)gemm_qkv,
        cudaFuncAttributeMaxDynamicSharedMemorySize, GEMM_SMEM);
    cudaFuncSetAttribute((const void*)gemm_out,
        cudaFuncAttributeMaxDynamicSharedMemorySize, GEMM_SMEM);
    cudaFuncSetAttribute((const void*)attn_mma,
        cudaFuncAttributeMaxDynamicSharedMemorySize, ATTN_SMEM);

    prep_all<<<8208, 256>>>(query, q_w, k_w, v_w, out_w,
                            rel_emb, bias_k, bias_v);                    // 1
    gemm_qkv<<<dim3(24, 16), 512, GEMM_SMEM>>>(Ahi, Alo, q_b, k_b, v_b); // 2
    attn_mma<<<dim3(8, 64), 128, ATTN_SMEM>>>(grep_w, grep_b, grep_a);   // 3
    gemm_out<<<dim3(8, 16), 512, GEMM_SMEM>>>(                           // 4
        Ahi, Alo, Whi + 3 * wsz, Wlo + 3 * wsz, out_b, out);
}

// round 16
// speedup vs baseline: 1.8470x; 1.2030x over previous
#include <cuda_runtime.h>
#include <cuda_bf16.h>
#include <cuda_fp16.h>
#include <cstdint>

// ---------------------------------------------------------------- constants
#define T_   1024
#define BZ   4
#define E_   1024
#define NH   16
#define HD   64
#define BH   64
#define SLEN 1025
#define M_   4096
#define LOG2E 1.44269504f
#define QSCALE2 (0.00390625f * LOG2E)
#define GATE_SC (256.0f / LOG2E)

// GEMM tiling: CTA 256x128, 16 warps (8x2), warp 32x64, K-chunk 32 fp16
#define GROWB 80
#define SA_SZ (256 * GROWB)             // 20480 (single A tile)
#define SB_SZ (128 * GROWB)             // 10240
#define SB_OFF SA_SZ                    // B tiles follow A
#define HSTAGE (SA_SZ + 2 * SB_SZ)      // 40960 (heavy: A, Bh, Bl)
#define LSTAGE (SA_SZ + SB_SZ)          // 30720 (light: A, Bh)
#define GEMM_SMEM (3 * HSTAGE)          // 122880

// attention smem: 128-row Q tile + gates + pb row + 2 stages x {K, VH, VL}
#define AROW  144
#define ATILE (64 * AROW)               // 9216
#define A_GT  18432                     // gate[128], gws[64], misc[2]
#define A_PB  19456                     // pb row: 2048 f32 = 8192 B
#define A_ST  27648
#define A_STB (3 * ATILE)               // 27648
#define ATTN_SMEM (A_ST + 2 * A_STB)    // 82944

#define KVSZ ((size_t)BH * SLEN * HD + 8192)

// ---------------------------------------------------------------- scratch
__device__ __half g_Q16[(size_t)BH * T_ * HD];
__device__ __half g_K16[KVSZ];
__device__ __half g_Vh16[KVSZ], g_Vl16[KVSZ];
__device__ float g_pb[(size_t)NH * 2048];

__device__ __half g_A16[(size_t)M_ * E_];          // GEMM A (query, then O)
__device__ __half g_Wh16[4][(size_t)E_ * E_];      // fp16 weight hi
__device__ __half g_Wl16[4][(size_t)E_ * E_];      // fp16 weight lo

// ---------------------------------------------------------------- helpers
__device__ __forceinline__ uint32_t cvta_smem(const void* p) {
    uint32_t a;
    asm("{ .reg .u64 t; cvta.to.shared.u64 t, %1; cvt.u32.u64 %0, t; }"
        : "=r"(a) : "l"(p));
    return a;
}

#define CP16(dst, src) \
    asm volatile("cp.async.cg.shared.global [%0], [%1], 16;" \
        :: "r"(dst), "l"(src) : "memory")
#define CPCOMMIT() asm volatile("cp.async.commit_group;" ::: "memory")
#define CPWAIT1()  asm volatile("cp.async.wait_group 1;" ::: "memory")
#define CPWAIT0()  asm volatile("cp.async.wait_group 0;" ::: "memory")

__device__ __forceinline__ void ldsm_x4(uint32_t r[4], uint32_t addr) {
    asm volatile(
        "ldmatrix.sync.aligned.m8n8.x4.shared.b16 {%0,%1,%2,%3}, [%4];"
        : "=r"(r[0]), "=r"(r[1]), "=r"(r[2]), "=r"(r[3]) : "r"(addr));
}
__device__ __forceinline__ void ldsm_x4_t(uint32_t r[4], uint32_t addr) {
    asm volatile(
        "ldmatrix.sync.aligned.m8n8.x4.trans.shared.b16 {%0,%1,%2,%3}, [%4];"
        : "=r"(r[0]), "=r"(r[1]), "=r"(r[2]), "=r"(r[3]) : "r"(addr));
}

// fp16 mma
__device__ __forceinline__ void mma16816h(float c[4], const uint32_t a[4],
                                          uint32_t b0, uint32_t b1) {
    asm volatile(
        "mma.sync.aligned.m16n8k16.row.col.f32.f16.f16.f32 "
        "{%0,%1,%2,%3}, {%4,%5,%6,%7}, {%8,%9}, {%0,%1,%2,%3};"
        : "+f"(c[0]), "+f"(c[1]), "+f"(c[2]), "+f"(c[3])
        : "r"(a[0]), "r"(a[1]), "r"(a[2]), "r"(a[3]), "r"(b0), "r"(b1));
}

__device__ __forceinline__ float ex2f(float x) {
    float y;
    asm("ex2.approx.f32 %0, %1;" : "=f"(y) : "f"(x));
    return y;
}

__device__ __forceinline__ uint32_t pack2h(float x, float y) {
    __half2 t = __float22half2_rn(make_float2(x, y));
    return *reinterpret_cast<uint32_t*>(&t);
}

// packed fp16x2 split
__device__ __forceinline__ void split2h(float x, float y,
                                        uint32_t& hi, uint32_t& lo) {
    __half2 h2 = __float22half2_rn(make_float2(x, y));
    float2 hf = __half22float2(h2);
    __half2 l2 = __float22half2_rn(make_float2(x - hf.x, y - hf.y));
    hi = *reinterpret_cast<uint32_t*>(&h2);
    lo = *reinterpret_cast<uint32_t*>(&l2);
}

// ---------------------------------------------------------------- prep_all
__global__ __launch_bounds__(256)
void prep_all(const float* __restrict__ query,
              const float* __restrict__ w0, const float* __restrict__ w1,
              const float* __restrict__ w2, const float* __restrict__ w3,
              const float* __restrict__ rel_emb,
              const float* __restrict__ bias_k,
              const float* __restrict__ bias_v)
{
    __shared__ float tile[32][33];
    int bid = blockIdx.x;
    int tid = threadIdx.x;

    if (bid < 4096) {
        int i = bid * 256 + tid;
        float4 v = reinterpret_cast<const float4*>(query)[i];
        uint32_t* ap = reinterpret_cast<uint32_t*>(g_A16);
        ap[2 * i]     = pack2h(v.x, v.y);
        ap[2 * i + 1] = pack2h(v.z, v.w);
    } else if (bid < 8192) {
        int b2 = bid - 4096;
        int z = b2 >> 10;
        int rem = b2 & 1023;
        int bx = (rem & 31) * 32, by = (rem >> 5) * 32;
        int tx = tid & 31, ty = tid >> 5;
        const float* W = (z == 0) ? w0 : (z == 1) ? w1 : (z == 2) ? w2 : w3;
        __half* hi = g_Wh16[z];
        __half* lo = g_Wl16[z];
        #pragma unroll
        for (int r = 0; r < 4; r++)
            tile[ty + r * 8][tx] = W[(size_t)(by + ty + r * 8) * E_ + bx + tx];
        __syncthreads();
        #pragma unroll
        for (int r = 0; r < 4; r++) {
            int n = bx + ty + r * 8, k = by + tx;
            float v = tile[tx][ty + r * 8];
            __half h = __float2half(v);
            hi[(size_t)n * E_ + k] = h;
            lo[(size_t)n * E_ + k] = __float2half(v - __half2float(h));
        }
    } else {
        int i = (bid - 8192) * 256 + tid;
        if (i < 2048) {
            int rel = i - 1023;
            int bkt = rel > 0 ? 16 : 0;
            int a = rel < 0 ? -rel : rel;
            int bu;
            if (a < 8) {
                bu = a;
            } else {
                float lf = logf((float)a * 0.125f + 1e-6f)
                           * (8.0f / 2.772588722239781f);
                int large = 8 + (int)lf;
                bu = large < 15 ? large : 15;
            }
            int bucket = bkt + bu;
            #pragma unroll
            for (int h = 0; h < NH; h++)
                g_pb[h * 2048 + i] = rel_emb[bucket * NH + h] * LOG2E;
        }
        int b = i >> 10, h = (i >> 6) & 15, d = i & 63;
        int x = b * 16 + 15;
        int y = 1009 + h;
        size_t idx = ((size_t)x * SLEN + y) * HD + d;
        float kv = bias_k[h * HD + d];
        float vv = bias_v[h * HD + d];
        __half vh = __float2half(vv);
        g_K16[idx] = __float2half(kv);
        g_Vh16[idx] = vh;
        g_Vl16[idx] = __float2half(vv - __half2float(vh));
    }
}

// ---------------------------------------------------------------- fused QKV GEMM
// grid (24, 16): bn 0-7 -> V proj (heavy, A * (Wh + Wl), fp16 output hi/lo)
//                bn 8-15 -> Q proj (light), bn 16-23 -> K proj (light)
__global__ __launch_bounds__(512, 1)
void gemm_qkv(const __half* __restrict__ A16,
              const float* __restrict__ q_b,
              const float* __restrict__ k_b,
              const float* __restrict__ v_b)
{
    extern __shared__ __align__(16) char sm_[];
    const int tid = threadIdx.x, lane = tid & 31, w = tid >> 5;
    const int bn = blockIdx.x, bm = blockIdx.y;
    const uint32_t smem_u = cvta_smem(sm_);

    const int wm = w >> 1, wn = w & 1;
    const int m0 = wm * 32, n0 = wn * 64;
    const int gid = lane >> 2, tig = lane & 3;
    const int mat = lane >> 3, rowin = lane & 7;
    const int a_row = rowin + (mat & 1) * 8;
    const int a_kof = (mat >> 1) * 16;
    const int b_row = rowin + (mat >> 1) * 8;
    const int b_kof = (mat & 1) * 16;

    const char* gA = (const char*)(A16 + (size_t)(bm * 256) * 1024);

    if (bn < 8) {
        // ---------------- heavy path: V projection, 2-term fp16
        const char* gB0 = (const char*)(g_Wh16[2] + (size_t)(bn * 128) * 1024);
        const char* gB1 = (const char*)(g_Wl16[2] + (size_t)(bn * 128) * 1024);

        auto load_stage = [&](int it, int buf) {
            uint32_t sb = smem_u + buf * HSTAGE;
            const int kb = it * 64;
            #pragma unroll
            for (int i = 0; i < 4; i++) {
                int idx = tid + i * 512;
                if (idx < 1024) {
                    int row = idx >> 2, c = idx & 3;
                    CP16(sb + row * GROWB + c * 16,
                         gA + (size_t)row * 2048 + kb + c * 16);
                } else {
                    int i2 = idx - 1024;
                    int tile = i2 >> 9, row = (i2 >> 2) & 127, c = i2 & 3;
                    const char* g = (tile ? gB1 : gB0)
                                    + (size_t)row * 2048 + kb + c * 16;
                    CP16(sb + SB_OFF + tile * SB_SZ + row * GROWB + c * 16, g);
                }
            }
            CPCOMMIT();
        };

        float acc[2][8][4] = {};
        load_stage(0, 0);
        load_stage(1, 1);

        for (int it = 0; it < 32; it++) {
            int buf = it % 3;
            if (it < 31) { CPWAIT1(); } else { CPWAIT0(); }
            __syncthreads();
            uint32_t sb = smem_u + buf * HSTAGE;
            #pragma unroll
            for (int ks = 0; ks < 2; ks++) {
                uint32_t af[2][4];
                #pragma unroll
                for (int mt = 0; mt < 2; mt++)
                    ldsm_x4(af[mt], sb + (m0 + mt * 16 + a_row) * GROWB
                                    + ks * 32 + a_kof);
                #pragma unroll
                for (int np = 0; np < 4; np++) {
                    uint32_t br = sb + SB_OFF
                                  + (n0 + np * 16 + b_row) * GROWB
                                  + ks * 32 + b_kof;
                    uint32_t bhi[4], blo[4];
                    ldsm_x4(bhi, br);
                    ldsm_x4(blo, br + SB_SZ);
                    #pragma unroll
                    for (int h = 0; h < 2; h++)
                        #pragma unroll
                        for (int mt = 0; mt < 2; mt++)
                            mma16816h(acc[mt][np * 2 + h], af[mt],
                                      bhi[2 * h], bhi[2 * h + 1]);
                    #pragma unroll
                    for (int h = 0; h < 2; h++)
                        #pragma unroll
                        for (int mt = 0; mt < 2; mt++)
                            mma16816h(acc[mt][np * 2 + h], af[mt],
                                      blo[2 * h], blo[2 * h + 1]);
                }
            }
            if (it + 2 < 32) load_stage(it + 2, (it + 2) % 3);
        }

        #pragma unroll
        for (int mt = 0; mt < 2; mt++) {
            #pragma unroll
            for (int nt = 0; nt < 8; nt++) {
                int n = bn * 128 + n0 + nt * 8 + tig * 2;
                float bx = v_b[n], by = v_b[n + 1];
                #pragma unroll
                for (int half = 0; half < 2; half++) {
                    int m = bm * 256 + m0 + mt * 16 + gid + half * 8;
                    float vx = acc[mt][nt][half * 2 + 0] + bx;
                    float vy = acc[mt][nt][half * 2 + 1] + by;
                    int t = m >> 2, b = m & 3;
                    int h = n >> 6, d = n & 63;
                    int u = t * 16 + h;
                    int x = b * 16 + u / 1025;
                    int y = u % 1025;
                    size_t idx = ((size_t)x * SLEN + y) * HD + d;
                    uint32_t hi, lo;
                    split2h(vx, vy, hi, lo);
                    *reinterpret_cast<uint32_t*>(&g_Vh16[idx]) = hi;
                    *reinterpret_cast<uint32_t*>(&g_Vl16[idx]) = lo;
                }
            }
        }
    } else {
        // ---------------- light path: Q / K projection (Wh only)
        const int bl = bn - 8;
        const int sel = bl >> 3;                 // 0=Q, 1=K
        const char* gB0 = (const char*)(g_Wh16[sel]
                          + (size_t)((bl & 7) * 128) * 1024);

        auto load_l = [&](int it, int buf) {
            uint32_t sb = smem_u + buf * LSTAGE;
            const int kb = it * 64;
            #pragma unroll
            for (int i = 0; i < 3; i++) {
                int idx = tid + i * 512;
                if (idx < 1024) {
                    int row = idx >> 2, c = idx & 3;
                    CP16(sb + row * GROWB + c * 16,
                         gA + (size_t)row * 2048 + kb + c * 16);
                } else {
                    int i2 = idx - 1024;
                    int row = i2 >> 2, c = i2 & 3;
                    CP16(sb + SB_OFF + row * GROWB + c * 16,
                         gB0 + (size_t)row * 2048 + kb + c * 16);
                }
            }
            CPCOMMIT();
        };

        float acc[2][8][4] = {};
        load_l(0, 0);
        load_l(1, 1);

        for (int it = 0; it < 32; it++) {
            int buf = it % 3;
            if (it < 31) { CPWAIT1(); } else { CPWAIT0(); }
            __syncthreads();
            uint32_t sb = smem_u + buf * LSTAGE;
            #pragma unroll
            for (int ks = 0; ks < 2; ks++) {
                uint32_t af[2][4];
                #pragma unroll
                for (int mt = 0; mt < 2; mt++)
                    ldsm_x4(af[mt], sb + (m0 + mt * 16 + a_row) * GROWB
                                    + ks * 32 + a_kof);
                #pragma unroll
                for (int np = 0; np < 4; np++) {
                    uint32_t bhi[4];
                    ldsm_x4(bhi, sb + SB_OFF
                                 + (n0 + np * 16 + b_row) * GROWB
                                 + ks * 32 + b_kof);
                    #pragma unroll
                    for (int h = 0; h < 2; h++)
                        #pragma unroll
                        for (int mt = 0; mt < 2; mt++)
                            mma16816h(acc[mt][np * 2 + h], af[mt],
                                      bhi[2 * h], bhi[2 * h + 1]);
                }
            }
            if (it + 2 < 32) load_l(it + 2, (it + 2) % 3);
        }

        const float* bias = (sel == 0) ? q_b : k_b;
        #pragma unroll
        for (int mt = 0; mt < 2; mt++) {
            #pragma unroll
            for (int nt = 0; nt < 8; nt++) {
                int n = (bl & 7) * 128 + n0 + nt * 8 + tig * 2;
                float bx = bias[n], by = bias[n + 1];
                #pragma unroll
                for (int half = 0; half < 2; half++) {
                    int m = bm * 256 + m0 + mt * 16 + gid + half * 8;
                    float vx = acc[mt][nt][half * 2 + 0] + bx;
                    float vy = acc[mt][nt][half * 2 + 1] + by;
                    int t = m >> 2, b = m & 3;
                    int h = n >> 6, d = n & 63;
                    if (sel == 0) {
                        int x = b * 16 + (t >> 6);
                        int y = ((t & 63) << 4) | h;
                        size_t idx = ((size_t)x * T_ + y) * HD + d;
                        *reinterpret_cast<uint32_t*>(&g_Q16[idx]) =
                            pack2h(vx * QSCALE2, vy * QSCALE2);
                    } else {
                        int u = t * 16 + h;
                        int x = b * 16 + u / 1025;
                        int y = u % 1025;
                        size_t idx = ((size_t)x * SLEN + y) * HD + d;
                        *reinterpret_cast<uint32_t*>(&g_K16[idx]) =
                            pack2h(vx, vy);
                    }
                }
            }
        }
    }
}

// ---------------------------------------------------------------- out proj GEMM
// C = A16 @ (Wh + Wl)^T + bias, 2-term fp16
__global__ __launch_bounds__(512, 1)
void gemm_out(const __half* __restrict__ A16,
              const __half* __restrict__ Bh,
              const __half* __restrict__ Bl,
              const float* __restrict__ bias,
              float* __restrict__ Cout)
{
    extern __shared__ __align__(16) char sm_[];
    const int tid = threadIdx.x, lane = tid & 31, w = tid >> 5;
    const int bn = blockIdx.x, bm = blockIdx.y;
    const uint32_t smem_u = cvta_smem(sm_);

    const int wm = w >> 1, wn = w & 1;
    const int m0 = wm * 32, n0 = wn * 64;
    const int gid = lane >> 2, tig = lane & 3;
    const int mat = lane >> 3, rowin = lane & 7;
    const int a_row = rowin + (mat & 1) * 8;
    const int a_kof = (mat >> 1) * 16;
    const int b_row = rowin + (mat >> 1) * 8;
    const int b_kof = (mat & 1) * 16;

    const char* gA  = (const char*)(A16 + (size_t)(bm * 256) * 1024);
    const char* gB0 = (const char*)(Bh + (size_t)(bn * 128) * 1024);
    const char* gB1 = (const char*)(Bl + (size_t)(bn * 128) * 1024);

    auto load_stage = [&](int it, int buf) {
        uint32_t sb = smem_u + buf * HSTAGE;
        const int kb = it * 64;
        #pragma unroll
        for (int i = 0; i < 4; i++) {
            int idx = tid + i * 512;
            if (idx < 1024) {
                int row = idx >> 2, c = idx & 3;
                CP16(sb + row * GROWB + c * 16,
                     gA + (size_t)row * 2048 + kb + c * 16);
            } else {
                int i2 = idx - 1024;
                int tile = i2 >> 9, row = (i2 >> 2) & 127, c = i2 & 3;
                const char* g = (tile ? gB1 : gB0)
                                + (size_t)row * 2048 + kb + c * 16;
                CP16(sb + SB_OFF + tile * SB_SZ + row * GROWB + c * 16, g);
            }
        }
        CPCOMMIT();
    };

    float acc[2][8][4] = {};
    load_stage(0, 0);
    load_stage(1, 1);

    for (int it = 0; it < 32; it++) {
        int buf = it % 3;
        if (it < 31) { CPWAIT1(); } else { CPWAIT0(); }
        __syncthreads();
        uint32_t sb = smem_u + buf * HSTAGE;
        #pragma unroll
        for (int ks = 0; ks < 2; ks++) {
            uint32_t af[2][4];
            #pragma unroll
            for (int mt = 0; mt < 2; mt++)
                ldsm_x4(af[mt], sb + (m0 + mt * 16 + a_row) * GROWB
                                + ks * 32 + a_kof);
            #pragma unroll
            for (int np = 0; np < 4; np++) {
                uint32_t br = sb + SB_OFF + (n0 + np * 16 + b_row) * GROWB
                              + ks * 32 + b_kof;
                uint32_t bhi[4], blo[4];
                ldsm_x4(bhi, br);
                ldsm_x4(blo, br + SB_SZ);
                #pragma unroll
                for (int h = 0; h < 2; h++)
                    #pragma unroll
                    for (int mt = 0; mt < 2; mt++)
                        mma16816h(acc[mt][np * 2 + h], af[mt],
                                  bhi[2 * h], bhi[2 * h + 1]);
                #pragma unroll
                for (int h = 0; h < 2; h++)
                    #pragma unroll
                    for (int mt = 0; mt < 2; mt++)
                        mma16816h(acc[mt][np * 2 + h], af[mt],
                                  blo[2 * h], blo[2 * h + 1]);
            }
        }
        if (it + 2 < 32) load_stage(it + 2, (it + 2) % 3);
    }

    #pragma unroll
    for (int mt = 0; mt < 2; mt++) {
        #pragma unroll
        for (int nt = 0; nt < 8; nt++) {
            int n = bn * 128 + n0 + nt * 8 + tig * 2;
            float bx = bias[n], by = bias[n + 1];
            #pragma unroll
            for (int half = 0; half < 2; half++) {
                int m = bm * 256 + m0 + mt * 16 + gid + half * 8;
                *reinterpret_cast<float2*>(&Cout[(size_t)m * E_ + n]) =
                    make_float2(acc[mt][nt][half * 2 + 0] + bx,
                                acc[mt][nt][half * 2 + 1] + by);
            }
        }
    }
}

// ---------------------------------------------------------------- attention
// 128 q-rows per CTA, 4 warps x 32 q-rows, 128 threads, 2 CTAs/SM. All fp16.
// QK^T: 1-term. PV: P single + V hi/lo (2 terms).
__global__ __launch_bounds__(128, 2)
void attn_mma(const float* __restrict__ grep_w,
              const float* __restrict__ grep_b,
              const float* __restrict__ grep_a)
{
    extern __shared__ __align__(16) char asmm[];
    const uint32_t smem_u = cvta_smem(asmm);
    const int tid = threadIdx.x, lane = tid & 31, w = tid >> 5;
    const int gid = lane >> 2, tig = lane & 3;
    const int mat = lane >> 3, rowin = lane & 7;
    const int x = blockIdx.y, t0 = blockIdx.x * 128;
    const int hx = x & 15, bx = x >> 4;

    float* gate_s = reinterpret_cast<float*>(asmm + A_GT);   // [128]
    float* gws_s  = gate_s + 128;                             // [64]
    float* misc_s = gws_s + 64;                               // [2]
    float* pb_s   = reinterpret_cast<float*>(asmm + A_PB);    // [2048]

    if (tid < 64) {
        float s = 0.f;
        #pragma unroll
        for (int j = 0; j < 8; j++) s += grep_w[tid * 8 + j];
        gws_s[tid] = s;
    }
    if (tid == 64) {
        float s = 0.f;
        #pragma unroll
        for (int j = 0; j < 8; j++) s += grep_b[j];
        misc_s[0] = s;
    }
    if (tid == 65) misc_s[1] = grep_a[hx];

    // Q tile (128 rows x 128B) + pb row (8KB)
    {
        const char* srcH = (const char*)g_Q16 + ((size_t)x * T_ + t0) * HD * 2;
        #pragma unroll
        for (int i = 0; i < 8; i++) {
            int idx = tid + i * 128;
            int row = idx >> 3, c = idx & 7;
            CP16(smem_u + row * AROW + c * 16,
                 srcH + (size_t)row * 128 + c * 16);
        }
        const char* pbg = (const char*)(g_pb + (size_t)hx * 2048);
        #pragma unroll
        for (int i = 0; i < 4; i++) {
            int idx = tid + i * 128;
            CP16(smem_u + A_PB + idx * 16, pbg + idx * 16);
        }
        CPCOMMIT();
    }

    const char* pK  = (const char*)g_K16  + (size_t)x * SLEN * HD * 2;
    const char* pVh = (const char*)g_Vh16 + (size_t)x * SLEN * HD * 2;
    const char* pVl = (const char*)g_Vl16 + (size_t)x * SLEN * HD * 2;

    auto load_kv = [&](int ch, int buf) {
        int s0 = ch * 64;
        #pragma unroll
        for (int i = 0; i < 12; i++) {
            int idx = tid + i * 128;
            int tile = idx >> 9, row = (idx >> 3) & 63, c = idx & 7;
            const char* p = (tile == 0) ? pK : (tile == 1) ? pVh : pVl;
            CP16(smem_u + A_ST + buf * A_STB + tile * ATILE
                 + row * AROW + c * 16,
                 p + (size_t)(s0 + row) * 128 + c * 16);
        }
        CPCOMMIT();
    };

    load_kv(0, 0);

    CPWAIT1();
    __syncthreads();
    {
        const __half* qr =
            reinterpret_cast<const __half*>(asmm + tid * AROW);
        float s = 0.f;
        #pragma unroll
        for (int d2 = 0; d2 < 64; d2++)
            s += __half2float(qr[d2]) * gws_s[d2];
        gate_s[tid] = misc_s[1] /
                      (1.f + __expf(-(s * GATE_SC + misc_s[0])));
    }

    float l[2][2] = {};
    float o[2][8][4] = {};
    uint32_t qh[4][2][4];
    const int tgm0 = t0 + w * 32 + gid;
    float g0[2], g1[2];

    // ---------------- main loop: chunks 0..15 (all full, unmasked)
    for (int ch = 0; ch < 16; ch++) {
        int buf = ch & 1;
        load_kv(ch + 1, buf ^ 1);
        CPWAIT1();
        __syncthreads();

        if (ch == 0) {
            #pragma unroll
            for (int ks = 0; ks < 4; ks++)
                #pragma unroll
                for (int mt = 0; mt < 2; mt++)
                    ldsm_x4(qh[ks][mt], smem_u
                            + (w * 32 + mt * 16 + rowin + (mat & 1) * 8) * AROW
                            + ks * 32 + (mat >> 1) * 16);
            #pragma unroll
            for (int mt = 0; mt < 2; mt++) {
                g0[mt] = gate_s[w * 32 + mt * 16 + gid];
                g1[mt] = gate_s[w * 32 + mt * 16 + gid + 8];
            }
        }

        const uint32_t kb = smem_u + A_ST + buf * A_STB;

        // S = Q K^T
        float s_acc[2][8][4] = {};
        #pragma unroll
        for (int ks = 0; ks < 4; ks++) {
            #pragma unroll
            for (int np = 0; np < 4; np++) {
                uint32_t khf[4];
                ldsm_x4(khf, kb + (np * 16 + rowin + (mat >> 1) * 8) * AROW
                             + ks * 32 + (mat & 1) * 16);
                #pragma unroll
                for (int h2 = 0; h2 < 2; h2++)
                    #pragma unroll
                    for (int mt = 0; mt < 2; mt++)
                        mma16816h(s_acc[mt][np * 2 + h2], qh[ks][mt],
                                  khf[2 * h2], khf[2 * h2 + 1]);
            }
        }

        // gated pos-bias + ex2
        int s0 = ch * 64;
        #pragma unroll
        for (int mt = 0; mt < 2; mt++) {
            const int base = s0 + tig * 2 + 1023 - (tgm0 + mt * 16);
            #pragma unroll
            for (int nt = 0; nt < 8; nt++) {
                float p0 = ex2f(s_acc[mt][nt][0] + g0[mt] * pb_s[base + nt * 8]);
                float p1 = ex2f(s_acc[mt][nt][1] + g0[mt] * pb_s[base + nt * 8 + 1]);
                float p2 = ex2f(s_acc[mt][nt][2] + g1[mt] * pb_s[base + nt * 8 - 8]);
                float p3 = ex2f(s_acc[mt][nt][3] + g1[mt] * pb_s[base + nt * 8 - 7]);
                s_acc[mt][nt][0] = p0; s_acc[mt][nt][1] = p1;
                s_acc[mt][nt][2] = p2; s_acc[mt][nt][3] = p3;
                l[mt][0] += p0 + p1; l[mt][1] += p2 + p3;
            }
        }

        // O += P V (fp16: P single, V hi/lo)
        const uint32_t vbh = kb + ATILE;
        const uint32_t vbl = kb + 2 * ATILE;
        #pragma unroll
        for (int ks = 0; ks < 4; ks++) {
            uint32_t ap[2][4];
            #pragma unroll
            for (int mt = 0; mt < 2; mt++)
                #pragma unroll
                for (int q = 0; q < 4; q++) {
                    int nt = 2 * ks + (q >> 1);
                    ap[mt][q] = pack2h(s_acc[mt][nt][(q & 1) * 2],
                                       s_acc[mt][nt][(q & 1) * 2 + 1]);
                }
            #pragma unroll
            for (int np = 0; np < 4; np++) {
                uint32_t va_off = (ks * 16 + rowin + (mat & 1) * 8) * AROW
                                  + (np * 16 + (mat >> 1) * 8) * 2;
                uint32_t vhf[4], vlf[4];
                ldsm_x4_t(vhf, vbh + va_off);
                ldsm_x4_t(vlf, vbl + va_off);
                #pragma unroll
                for (int mt = 0; mt < 2; mt++) {
                    #pragma unroll
                    for (int h2 = 0; h2 < 2; h2++)
                        mma16816h(o[mt][np * 2 + h2], ap[mt],
                                  vhf[2 * h2], vhf[2 * h2 + 1]);
                    #pragma unroll
                    for (int h2 = 0; h2 < 2; h2++)
                        mma16816h(o[mt][np * 2 + h2], ap[mt],
                                  vlf[2 * h2], vlf[2 * h2 + 1]);
                }
            }
        }
        __syncthreads();
    }

    // ---------------- tail: chunk 16 — only key 1024 is valid
    {
        CPWAIT0();
        __syncthreads();
        const uint32_t kb = smem_u + A_ST + 0 * A_STB;   // buf = 16 & 1 = 0

        float s16[2][2][4] = {};
        #pragma unroll
        for (int ks = 0; ks < 4; ks++) {
            uint32_t khf[4];
            ldsm_x4(khf, kb + (rowin + (mat >> 1) * 8) * AROW
                         + ks * 32 + (mat & 1) * 16);
            #pragma unroll
            for (int h2 = 0; h2 < 2; h2++)
                #pragma unroll
                for (int mt = 0; mt < 2; mt++)
                    mma16816h(s16[mt][h2], qh[ks][mt],
                              khf[2 * h2], khf[2 * h2 + 1]);
        }
        #pragma unroll
        for (int mt = 0; mt < 2; mt++) {
            #pragma unroll
            for (int j = 0; j < 4; j += 2) {
                float p = 0.f;
                if (tig == 0) {
                    int tg = tgm0 + mt * 16 + (j >> 1) * 8;
                    float g = (j >> 1) ? g1[mt] : g0[mt];
                    p = ex2f(s16[mt][0][j] + g * pb_s[2047 - tg]);
                }
                s16[mt][0][j] = p;
                if (j < 2) l[mt][0] += p; else l[mt][1] += p;
            }
            s16[mt][0][1] = 0.f; s16[mt][0][3] = 0.f;
            s16[mt][1][0] = 0.f; s16[mt][1][1] = 0.f;
            s16[mt][1][2] = 0.f; s16[mt][1][3] = 0.f;
        }
        const uint32_t vbh = kb + ATILE;
        const uint32_t vbl = kb + 2 * ATILE;
        uint32_t ap[2][4];
        #pragma unroll
        for (int mt = 0; mt < 2; mt++)
            #pragma unroll
            for (int q = 0; q < 4; q++) {
                int nt = q >> 1;
                ap[mt][q] = pack2h(s16[mt][nt][(q & 1) * 2],
                                   s16[mt][nt][(q & 1) * 2 + 1]);
            }
        #pragma unroll
        for (int np = 0; np < 4; np++) {
            uint32_t va_off = (rowin + (mat & 1) * 8) * AROW
                              + (np * 16 + (mat >> 1) * 8) * 2;
            uint32_t vhf[4], vlf[4];
            ldsm_x4_t(vhf, vbh + va_off);
            ldsm_x4_t(vlf, vbl + va_off);
            #pragma unroll
            for (int mt = 0; mt < 2; mt++) {
                #pragma unroll
                for (int h2 = 0; h2 < 2; h2++)
                    mma16816h(o[mt][np * 2 + h2], ap[mt],
                              vhf[2 * h2], vhf[2 * h2 + 1]);
                #pragma unroll
                for (int h2 = 0; h2 < 2; h2++)
                    mma16816h(o[mt][np * 2 + h2], ap[mt],
                              vlf[2 * h2], vlf[2 * h2 + 1]);
            }
        }
    }

    // ---- deferred row-sum reductions + epilogue (O -> single fp16)
    #pragma unroll
    for (int mt = 0; mt < 2; mt++) {
        l[mt][0] += __shfl_xor_sync(0xffffffffu, l[mt][0], 1);
        l[mt][0] += __shfl_xor_sync(0xffffffffu, l[mt][0], 2);
        l[mt][1] += __shfl_xor_sync(0xffffffffu, l[mt][1], 1);
        l[mt][1] += __shfl_xor_sync(0xffffffffu, l[mt][1], 2);
        float inv0 = 1.0f / l[mt][0], inv1 = 1.0f / l[mt][1];
        int y0 = tgm0 + mt * 16, y1 = y0 + 8;
        #pragma unroll
        for (int nt = 0; nt < 8; nt++) {
            int col = hx * 64 + nt * 8 + tig * 2;
            size_t i0 = (size_t)(y0 * BZ + bx) * E_ + col;
            *reinterpret_cast<uint32_t*>(&g_A16[i0]) =
                pack2h(o[mt][nt][0] * inv0, o[mt][nt][1] * inv0);
            size_t i1 = (size_t)(y1 * BZ + bx) * E_ + col;
            *reinterpret_cast<uint32_t*>(&g_A16[i1]) =
                pack2h(o[mt][nt][2] * inv1, o[mt][nt][3] * inv1);
        }
    }
}

// ---------------------------------------------------------------- host side
extern "C" void kernel_launch(void* const* d_in, const int* in_sizes, int n_in,
                              void* d_out, int out_size)
{
    (void)in_sizes; (void)n_in; (void)out_size;
    const float* query   = (const float*)d_in[0];
    const float* q_w     = (const float*)d_in[1];
    const float* q_b     = (const float*)d_in[2];
    const float* k_w     = (const float*)d_in[3];
    const float* k_b     = (const float*)d_in[4];
    const float* v_w     = (const float*)d_in[5];
    const float* v_b     = (const float*)d_in[6];
    const float* out_w   = (const float*)d_in[7];
    const float* out_b   = (const float*)d_in[8];
    const float* rel_emb = (const float*)d_in[9];
    const float* grep_w  = (const float*)d_in[10];
    const float* grep_b  = (const float*)d_in[11];
    const float* grep_a  = (const float*)d_in[12];
    const float* bias_k  = (const float*)d_in[13];
    const float* bias_v  = (const float*)d_in[14];
    float* out = (float*)d_out;

    void *pA, *pWh, *pWl;
    cudaGetSymbolAddress(&pA,  g_A16);
    cudaGetSymbolAddress(&pWh, g_Wh16);
    cudaGetSymbolAddress(&pWl, g_Wl16);

    __half* A16 = (__half*)pA;
    const size_t wsz = (size_t)E_ * E_;
    __half* Wh = (__half*)pWh;
    __half* Wl = (__half*)pWl;

    cudaFuncSetAttribute((const void*)gemm_qkv,
        cudaFuncAttributeMaxDynamicSharedMemorySize, GEMM_SMEM);
    cudaFuncSetAttribute((const void*)gemm_out,
        cudaFuncAttributeMaxDynamicSharedMemorySize, GEMM_SMEM);
    cudaFuncSetAttribute((const void*)attn_mma,
        cudaFuncAttributeMaxDynamicSharedMemorySize, ATTN_SMEM);

    prep_all<<<8208, 256>>>(query, q_w, k_w, v_w, out_w,
                            rel_emb, bias_k, bias_v);                  // 1
    gemm_qkv<<<dim3(24, 16), 512, GEMM_SMEM>>>(A16, q_b, k_b, v_b);    // 2
    attn_mma<<<dim3(8, 64), 128, ATTN_SMEM>>>(grep_w, grep_b, grep_a); // 3
    gemm_out<<<dim3(8, 16), 512, GEMM_SMEM>>>(                         // 4
        A16, Wh + 3 * wsz, Wl + 3 * wsz, out_b, out);
}

// round 17
// speedup vs baseline: 2.4117x; 1.3058x over previous
#include <cuda_runtime.h>
#include <cuda_fp16.h>
#include <cstdint>

// ---------------------------------------------------------------- constants
#define T_   1024
#define BZ   4
#define E_   1024
#define NH   16
#define HD   64
#define BH   64
#define SLEN 1025
#define M_   4096
#define LOG2E 1.44269504f
#define QSCALE2 (0.00390625f * LOG2E)
#define GATE_SC (256.0f / LOG2E)

// GEMM tiling: CTA 256x128, 16 warps (8x2), warp 32x64, K-chunk 32 fp16
#define GROWB 80
#define SA_SZ (256 * GROWB)             // 20480
#define SB_SZ (128 * GROWB)             // 10240
#define SB_OFF SA_SZ
#define LSTAGE (SA_SZ + SB_SZ)          // 30720 (A, Bh)
#define GEMM_SMEM (3 * LSTAGE)          // 92160

// attention smem: 128-row Q tile + gates + pb row + 2 stages x {K, V}
#define AROW  144
#define ATILE (64 * AROW)               // 9216
#define A_GT  18432                     // gate[128], gws[64], misc[2]
#define A_PB  19456                     // pb row: 2048 f32
#define A_ST  27648
#define A_STB (2 * ATILE)               // 18432
#define ATTN_SMEM (A_ST + 2 * A_STB)    // 64512

#define KVSZ ((size_t)BH * SLEN * HD + 8192)

// ---------------------------------------------------------------- scratch
__device__ __half g_Q16[(size_t)BH * T_ * HD];
__device__ __half g_K16[KVSZ];
__device__ __half g_V16[KVSZ];
__device__ float g_pb[(size_t)NH * 2048];

__device__ __half g_A16[(size_t)M_ * E_];          // GEMM A (query, then O)
__device__ __half g_Wh16[4][(size_t)E_ * E_];      // fp16 weights [n][k]

// ---------------------------------------------------------------- helpers
__device__ __forceinline__ uint32_t cvta_smem(const void* p) {
    uint32_t a;
    asm("{ .reg .u64 t; cvta.to.shared.u64 t, %1; cvt.u32.u64 %0, t; }"
        : "=r"(a) : "l"(p));
    return a;
}

#define CP16(dst, src) \
    asm volatile("cp.async.cg.shared.global [%0], [%1], 16;" \
        :: "r"(dst), "l"(src) : "memory")
#define CPCOMMIT() asm volatile("cp.async.commit_group;" ::: "memory")
#define CPWAIT1()  asm volatile("cp.async.wait_group 1;" ::: "memory")
#define CPWAIT0()  asm volatile("cp.async.wait_group 0;" ::: "memory")

__device__ __forceinline__ void ldsm_x4(uint32_t r[4], uint32_t addr) {
    asm volatile(
        "ldmatrix.sync.aligned.m8n8.x4.shared.b16 {%0,%1,%2,%3}, [%4];"
        : "=r"(r[0]), "=r"(r[1]), "=r"(r[2]), "=r"(r[3]) : "r"(addr));
}
__device__ __forceinline__ void ldsm_x4_t(uint32_t r[4], uint32_t addr) {
    asm volatile(
        "ldmatrix.sync.aligned.m8n8.x4.trans.shared.b16 {%0,%1,%2,%3}, [%4];"
        : "=r"(r[0]), "=r"(r[1]), "=r"(r[2]), "=r"(r[3]) : "r"(addr));
}

__device__ __forceinline__ void mma16816h(float c[4], const uint32_t a[4],
                                          uint32_t b0, uint32_t b1) {
    asm volatile(
        "mma.sync.aligned.m16n8k16.row.col.f32.f16.f16.f32 "
        "{%0,%1,%2,%3}, {%4,%5,%6,%7}, {%8,%9}, {%0,%1,%2,%3};"
        : "+f"(c[0]), "+f"(c[1]), "+f"(c[2]), "+f"(c[3])
        : "r"(a[0]), "r"(a[1]), "r"(a[2]), "r"(a[3]), "r"(b0), "r"(b1));
}

__device__ __forceinline__ float ex2f(float x) {
    float y;
    asm("ex2.approx.f32 %0, %1;" : "=f"(y) : "f"(x));
    return y;
}

__device__ __forceinline__ uint32_t pack2h(float x, float y) {
    __half2 t = __float22half2_rn(make_float2(x, y));
    return *reinterpret_cast<uint32_t*>(&t);
}

// ---------------------------------------------------------------- prep_all
__global__ __launch_bounds__(256)
void prep_all(const float* __restrict__ query,
              const float* __restrict__ w0, const float* __restrict__ w1,
              const float* __restrict__ w2, const float* __restrict__ w3,
              const float* __restrict__ rel_emb,
              const float* __restrict__ bias_k,
              const float* __restrict__ bias_v)
{
    __shared__ float tile[32][33];
    int bid = blockIdx.x;
    int tid = threadIdx.x;

    if (bid < 4096) {
        int i = bid * 256 + tid;
        float4 v = reinterpret_cast<const float4*>(query)[i];
        uint32_t* ap = reinterpret_cast<uint32_t*>(g_A16);
        ap[2 * i]     = pack2h(v.x, v.y);
        ap[2 * i + 1] = pack2h(v.z, v.w);
    } else if (bid < 8192) {
        int b2 = bid - 4096;
        int z = b2 >> 10;
        int rem = b2 & 1023;
        int bx = (rem & 31) * 32, by = (rem >> 5) * 32;
        int tx = tid & 31, ty = tid >> 5;
        const float* W = (z == 0) ? w0 : (z == 1) ? w1 : (z == 2) ? w2 : w3;
        __half* hi = g_Wh16[z];
        #pragma unroll
        for (int r = 0; r < 4; r++)
            tile[ty + r * 8][tx] = W[(size_t)(by + ty + r * 8) * E_ + bx + tx];
        __syncthreads();
        #pragma unroll
        for (int r = 0; r < 4; r++) {
            int n = bx + ty + r * 8, k = by + tx;
            hi[(size_t)n * E_ + k] = __float2half(tile[tx][ty + r * 8]);
        }
    } else {
        int i = (bid - 8192) * 256 + tid;
        if (i < 2048) {
            int rel = i - 1023;
            int bkt = rel > 0 ? 16 : 0;
            int a = rel < 0 ? -rel : rel;
            int bu;
            if (a < 8) {
                bu = a;
            } else {
                float lf = logf((float)a * 0.125f + 1e-6f)
                           * (8.0f / 2.772588722239781f);
                int large = 8 + (int)lf;
                bu = large < 15 ? large : 15;
            }
            int bucket = bkt + bu;
            #pragma unroll
            for (int h = 0; h < NH; h++)
                g_pb[h * 2048 + i] = rel_emb[bucket * NH + h] * LOG2E;
        }
        int b = i >> 10, h = (i >> 6) & 15, d = i & 63;
        int x = b * 16 + 15;
        int y = 1009 + h;
        size_t idx = ((size_t)x * SLEN + y) * HD + d;
        g_K16[idx] = __float2half(bias_k[h * HD + d]);
        g_V16[idx] = __float2half(bias_v[h * HD + d]);
    }
}

// ---------------------------------------------------------------- fused QKV GEMM
// grid (24, 16), all 1-term fp16: bn 0-7 -> V, 8-15 -> Q, 16-23 -> K
__global__ __launch_bounds__(512, 1)
void gemm_qkv(const __half* __restrict__ A16,
              const float* __restrict__ q_b,
              const float* __restrict__ k_b,
              const float* __restrict__ v_b)
{
    extern __shared__ __align__(16) char sm_[];
    const int tid = threadIdx.x, lane = tid & 31, w = tid >> 5;
    const int bn = blockIdx.x, bm = blockIdx.y;
    const uint32_t smem_u = cvta_smem(sm_);

    const int wm = w >> 1, wn = w & 1;
    const int m0 = wm * 32, n0 = wn * 64;
    const int gid = lane >> 2, tig = lane & 3;
    const int mat = lane >> 3, rowin = lane & 7;
    const int a_row = rowin + (mat & 1) * 8;
    const int a_kof = (mat >> 1) * 16;
    const int b_row = rowin + (mat >> 1) * 8;
    const int b_kof = (mat & 1) * 16;

    const int sel = bn >> 3;                 // 0=V, 1=Q, 2=K
    const __half* W = (sel == 0) ? g_Wh16[2]
                      : (sel == 1) ? g_Wh16[0] : g_Wh16[1];

    const char* gA  = (const char*)(A16 + (size_t)(bm * 256) * 1024);
    const char* gB0 = (const char*)(W + (size_t)((bn & 7) * 128) * 1024);

    auto load_l = [&](int it, int buf) {
        uint32_t sb = smem_u + buf * LSTAGE;
        const int kb = it * 64;
        #pragma unroll
        for (int i = 0; i < 3; i++) {
            int idx = tid + i * 512;
            if (idx < 1024) {
                int row = idx >> 2, c = idx & 3;
                CP16(sb + row * GROWB + c * 16,
                     gA + (size_t)row * 2048 + kb + c * 16);
            } else {
                int i2 = idx - 1024;
                int row = i2 >> 2, c = i2 & 3;
                CP16(sb + SB_OFF + row * GROWB + c * 16,
                     gB0 + (size_t)row * 2048 + kb + c * 16);
            }
        }
        CPCOMMIT();
    };

    float acc[2][8][4] = {};
    load_l(0, 0);
    load_l(1, 1);

    for (int it = 0; it < 32; it++) {
        int buf = it % 3;
        if (it < 31) { CPWAIT1(); } else { CPWAIT0(); }
        __syncthreads();
        uint32_t sb = smem_u + buf * LSTAGE;
        #pragma unroll
        for (int ks = 0; ks < 2; ks++) {
            uint32_t af[2][4];
            #pragma unroll
            for (int mt = 0; mt < 2; mt++)
                ldsm_x4(af[mt], sb + (m0 + mt * 16 + a_row) * GROWB
                                + ks * 32 + a_kof);
            #pragma unroll
            for (int np = 0; np < 4; np++) {
                uint32_t bhi[4];
                ldsm_x4(bhi, sb + SB_OFF + (n0 + np * 16 + b_row) * GROWB
                             + ks * 32 + b_kof);
                #pragma unroll
                for (int h = 0; h < 2; h++)
                    #pragma unroll
                    for (int mt = 0; mt < 2; mt++)
                        mma16816h(acc[mt][np * 2 + h], af[mt],
                                  bhi[2 * h], bhi[2 * h + 1]);
            }
        }
        if (it + 2 < 32) load_l(it + 2, (it + 2) % 3);
    }

    const float* bias = (sel == 0) ? v_b : (sel == 1) ? q_b : k_b;
    #pragma unroll
    for (int mt = 0; mt < 2; mt++) {
        #pragma unroll
        for (int nt = 0; nt < 8; nt++) {
            int n = (bn & 7) * 128 + n0 + nt * 8 + tig * 2;
            float bx = bias[n], by = bias[n + 1];
            #pragma unroll
            for (int half = 0; half < 2; half++) {
                int m = bm * 256 + m0 + mt * 16 + gid + half * 8;
                float vx = acc[mt][nt][half * 2 + 0] + bx;
                float vy = acc[mt][nt][half * 2 + 1] + by;
                int t = m >> 2, b = m & 3;
                int h = n >> 6, d = n & 63;
                if (sel == 1) {
                    int x = b * 16 + (t >> 6);
                    int y = ((t & 63) << 4) | h;
                    size_t idx = ((size_t)x * T_ + y) * HD + d;
                    *reinterpret_cast<uint32_t*>(&g_Q16[idx]) =
                        pack2h(vx * QSCALE2, vy * QSCALE2);
                } else {
                    int u = t * 16 + h;
                    int x = b * 16 + u / 1025;
                    int y = u % 1025;
                    size_t idx = ((size_t)x * SLEN + y) * HD + d;
                    __half* dst = (sel == 0) ? g_V16 : g_K16;
                    *reinterpret_cast<uint32_t*>(&dst[idx]) = pack2h(vx, vy);
                }
            }
        }
    }
}

// ---------------------------------------------------------------- out proj GEMM
// C = A16 @ Wh^T + bias, 1-term fp16
__global__ __launch_bounds__(512, 1)
void gemm_out(const __half* __restrict__ A16,
              const __half* __restrict__ Bh,
              const float* __restrict__ bias,
              float* __restrict__ Cout)
{
    extern __shared__ __align__(16) char sm_[];
    const int tid = threadIdx.x, lane = tid & 31, w = tid >> 5;
    const int bn = blockIdx.x, bm = blockIdx.y;
    const uint32_t smem_u = cvta_smem(sm_);

    const int wm = w >> 1, wn = w & 1;
    const int m0 = wm * 32, n0 = wn * 64;
    const int gid = lane >> 2, tig = lane & 3;
    const int mat = lane >> 3, rowin = lane & 7;
    const int a_row = rowin + (mat & 1) * 8;
    const int a_kof = (mat >> 1) * 16;
    const int b_row = rowin + (mat >> 1) * 8;
    const int b_kof = (mat & 1) * 16;

    const char* gA  = (const char*)(A16 + (size_t)(bm * 256) * 1024);
    const char* gB0 = (const char*)(Bh + (size_t)(bn * 128) * 1024);

    auto load_l = [&](int it, int buf) {
        uint32_t sb = smem_u + buf * LSTAGE;
        const int kb = it * 64;
        #pragma unroll
        for (int i = 0; i < 3; i++) {
            int idx = tid + i * 512;
            if (idx < 1024) {
                int row = idx >> 2, c = idx & 3;
                CP16(sb + row * GROWB + c * 16,
                     gA + (size_t)row * 2048 + kb + c * 16);
            } else {
                int i2 = idx - 1024;
                int row = i2 >> 2, c = i2 & 3;
                CP16(sb + SB_OFF + row * GROWB + c * 16,
                     gB0 + (size_t)row * 2048 + kb + c * 16);
            }
        }
        CPCOMMIT();
    };

    float acc[2][8][4] = {};
    load_l(0, 0);
    load_l(1, 1);

    for (int it = 0; it < 32; it++) {
        int buf = it % 3;
        if (it < 31) { CPWAIT1(); } else { CPWAIT0(); }
        __syncthreads();
        uint32_t sb = smem_u + buf * LSTAGE;
        #pragma unroll
        for (int ks = 0; ks < 2; ks++) {
            uint32_t af[2][4];
            #pragma unroll
            for (int mt = 0; mt < 2; mt++)
                ldsm_x4(af[mt], sb + (m0 + mt * 16 + a_row) * GROWB
                                + ks * 32 + a_kof);
            #pragma unroll
            for (int np = 0; np < 4; np++) {
                uint32_t bhi[4];
                ldsm_x4(bhi, sb + SB_OFF + (n0 + np * 16 + b_row) * GROWB
                             + ks * 32 + b_kof);
                #pragma unroll
                for (int h = 0; h < 2; h++)
                    #pragma unroll
                    for (int mt = 0; mt < 2; mt++)
                        mma16816h(acc[mt][np * 2 + h], af[mt],
                                  bhi[2 * h], bhi[2 * h + 1]);
            }
        }
        if (it + 2 < 32) load_l(it + 2, (it + 2) % 3);
    }

    #pragma unroll
    for (int mt = 0; mt < 2; mt++) {
        #pragma unroll
        for (int nt = 0; nt < 8; nt++) {
            int n = bn * 128 + n0 + nt * 8 + tig * 2;
            float bx = bias[n], by = bias[n + 1];
            #pragma unroll
            for (int half = 0; half < 2; half++) {
                int m = bm * 256 + m0 + mt * 16 + gid + half * 8;
                *reinterpret_cast<float2*>(&Cout[(size_t)m * E_ + n]) =
                    make_float2(acc[mt][nt][half * 2 + 0] + bx,
                                acc[mt][nt][half * 2 + 1] + by);
            }
        }
    }
}

// ---------------------------------------------------------------- attention
// 128 q-rows per CTA, 4 warps x 32 q-rows, 128 threads, 2 CTAs/SM.
// All plain fp16: QK^T 1-term, PV 1-term.
__global__ __launch_bounds__(128, 2)
void attn_mma(const float* __restrict__ grep_w,
              const float* __restrict__ grep_b,
              const float* __restrict__ grep_a)
{
    extern __shared__ __align__(16) char asmm[];
    const uint32_t smem_u = cvta_smem(asmm);
    const int tid = threadIdx.x, lane = tid & 31, w = tid >> 5;
    const int gid = lane >> 2, tig = lane & 3;
    const int mat = lane >> 3, rowin = lane & 7;
    const int x = blockIdx.y, t0 = blockIdx.x * 128;
    const int hx = x & 15, bx = x >> 4;

    float* gate_s = reinterpret_cast<float*>(asmm + A_GT);   // [128]
    float* gws_s  = gate_s + 128;                             // [64]
    float* misc_s = gws_s + 64;                               // [2]
    float* pb_s   = reinterpret_cast<float*>(asmm + A_PB);    // [2048]

    if (tid < 64) {
        float s = 0.f;
        #pragma unroll
        for (int j = 0; j < 8; j++) s += grep_w[tid * 8 + j];
        gws_s[tid] = s;
    }
    if (tid == 64) {
        float s = 0.f;
        #pragma unroll
        for (int j = 0; j < 8; j++) s += grep_b[j];
        misc_s[0] = s;
    }
    if (tid == 65) misc_s[1] = grep_a[hx];

    // Q tile (128 rows x 128B) + pb row (8KB)
    {
        const char* srcH = (const char*)g_Q16 + ((size_t)x * T_ + t0) * HD * 2;
        #pragma unroll
        for (int i = 0; i < 8; i++) {
            int idx = tid + i * 128;
            int row = idx >> 3, c = idx & 7;
            CP16(smem_u + row * AROW + c * 16,
                 srcH + (size_t)row * 128 + c * 16);
        }
        const char* pbg = (const char*)(g_pb + (size_t)hx * 2048);
        #pragma unroll
        for (int i = 0; i < 4; i++) {
            int idx = tid + i * 128;
            CP16(smem_u + A_PB + idx * 16, pbg + idx * 16);
        }
        CPCOMMIT();
    }

    const char* pK = (const char*)g_K16 + (size_t)x * SLEN * HD * 2;
    const char* pV = (const char*)g_V16 + (size_t)x * SLEN * HD * 2;

    auto load_kv = [&](int ch, int buf) {
        int s0 = ch * 64;
        #pragma unroll
        for (int i = 0; i < 8; i++) {
            int idx = tid + i * 128;
            int tile = idx >> 9, row = (idx >> 3) & 63, c = idx & 7;
            const char* p = tile ? pV : pK;
            CP16(smem_u + A_ST + buf * A_STB + tile * ATILE
                 + row * AROW + c * 16,
                 p + (size_t)(s0 + row) * 128 + c * 16);
        }
        CPCOMMIT();
    };

    load_kv(0, 0);

    CPWAIT1();
    __syncthreads();
    {
        const __half* qr = reinterpret_cast<const __half*>(asmm + tid * AROW);
        float s = 0.f;
        #pragma unroll
        for (int d2 = 0; d2 < 64; d2++)
            s += __half2float(qr[d2]) * gws_s[d2];
        gate_s[tid] = misc_s[1] /
                      (1.f + __expf(-(s * GATE_SC + misc_s[0])));
    }

    float l[2][2] = {};
    float o[2][8][4] = {};
    uint32_t qh[4][2][4];
    const int tgm0 = t0 + w * 32 + gid;
    float g0[2], g1[2];

    // ---------------- main loop: chunks 0..15
    for (int ch = 0; ch < 16; ch++) {
        int buf = ch & 1;
        load_kv(ch + 1, buf ^ 1);
        CPWAIT1();
        __syncthreads();

        if (ch == 0) {
            #pragma unroll
            for (int ks = 0; ks < 4; ks++)
                #pragma unroll
                for (int mt = 0; mt < 2; mt++)
                    ldsm_x4(qh[ks][mt], smem_u
                            + (w * 32 + mt * 16 + rowin + (mat & 1) * 8) * AROW
                            + ks * 32 + (mat >> 1) * 16);
            #pragma unroll
            for (int mt = 0; mt < 2; mt++) {
                g0[mt] = gate_s[w * 32 + mt * 16 + gid];
                g1[mt] = gate_s[w * 32 + mt * 16 + gid + 8];
            }
        }

        const uint32_t kb = smem_u + A_ST + buf * A_STB;

        // S = Q K^T
        float s_acc[2][8][4] = {};
        #pragma unroll
        for (int ks = 0; ks < 4; ks++) {
            #pragma unroll
            for (int np = 0; np < 4; np++) {
                uint32_t khf[4];
                ldsm_x4(khf, kb + (np * 16 + rowin + (mat >> 1) * 8) * AROW
                             + ks * 32 + (mat & 1) * 16);
                #pragma unroll
                for (int h2 = 0; h2 < 2; h2++)
                    #pragma unroll
                    for (int mt = 0; mt < 2; mt++)
                        mma16816h(s_acc[mt][np * 2 + h2], qh[ks][mt],
                                  khf[2 * h2], khf[2 * h2 + 1]);
            }
        }

        // gated pos-bias + ex2
        int s0 = ch * 64;
        #pragma unroll
        for (int mt = 0; mt < 2; mt++) {
            const int base = s0 + tig * 2 + 1023 - (tgm0 + mt * 16);
            #pragma unroll
            for (int nt = 0; nt < 8; nt++) {
                float p0 = ex2f(s_acc[mt][nt][0] + g0[mt] * pb_s[base + nt * 8]);
                float p1 = ex2f(s_acc[mt][nt][1] + g0[mt] * pb_s[base + nt * 8 + 1]);
                float p2 = ex2f(s_acc[mt][nt][2] + g1[mt] * pb_s[base + nt * 8 - 8]);
                float p3 = ex2f(s_acc[mt][nt][3] + g1[mt] * pb_s[base + nt * 8 - 7]);
                s_acc[mt][nt][0] = p0; s_acc[mt][nt][1] = p1;
                s_acc[mt][nt][2] = p2; s_acc[mt][nt][3] = p3;
                l[mt][0] += p0 + p1; l[mt][1] += p2 + p3;
            }
        }

        // O += P V (1-term fp16)
        const uint32_t vb = kb + ATILE;
        #pragma unroll
        for (int ks = 0; ks < 4; ks++) {
            uint32_t ap[2][4];
            #pragma unroll
            for (int mt = 0; mt < 2; mt++)
                #pragma unroll
                for (int q = 0; q < 4; q++) {
                    int nt = 2 * ks + (q >> 1);
                    ap[mt][q] = pack2h(s_acc[mt][nt][(q & 1) * 2],
                                       s_acc[mt][nt][(q & 1) * 2 + 1]);
                }
            #pragma unroll
            for (int np = 0; np < 4; np++) {
                uint32_t va_off = (ks * 16 + rowin + (mat & 1) * 8) * AROW
                                  + (np * 16 + (mat >> 1) * 8) * 2;
                uint32_t vhf[4];
                ldsm_x4_t(vhf, vb + va_off);
                #pragma unroll
                for (int mt = 0; mt < 2; mt++)
                    #pragma unroll
                    for (int h2 = 0; h2 < 2; h2++)
                        mma16816h(o[mt][np * 2 + h2], ap[mt],
                                  vhf[2 * h2], vhf[2 * h2 + 1]);
            }
        }
        __syncthreads();
    }

    // ---------------- tail: chunk 16 — only key 1024 is valid
    {
        CPWAIT0();
        __syncthreads();
        const uint32_t kb = smem_u + A_ST + 0 * A_STB;

        float s16[2][2][4] = {};
        #pragma unroll
        for (int ks = 0; ks < 4; ks++) {
            uint32_t khf[4];
            ldsm_x4(khf, kb + (rowin + (mat >> 1) * 8) * AROW
                         + ks * 32 + (mat & 1) * 16);
            #pragma unroll
            for (int h2 = 0; h2 < 2; h2++)
                #pragma unroll
                for (int mt = 0; mt < 2; mt++)
                    mma16816h(s16[mt][h2], qh[ks][mt],
                              khf[2 * h2], khf[2 * h2 + 1]);
        }
        #pragma unroll
        for (int mt = 0; mt < 2; mt++) {
            #pragma unroll
            for (int j = 0; j < 4; j += 2) {
                float p = 0.f;
                if (tig == 0) {
                    int tg = tgm0 + mt * 16 + (j >> 1) * 8;
                    float g = (j >> 1) ? g1[mt] : g0[mt];
                    p = ex2f(s16[mt][0][j] + g * pb_s[2047 - tg]);
                }
                s16[mt][0][j] = p;
                if (j < 2) l[mt][0] += p; else l[mt][1] += p;
            }
            s16[mt][0][1] = 0.f; s16[mt][0][3] = 0.f;
            s16[mt][1][0] = 0.f; s16[mt][1][1] = 0.f;
            s16[mt][1][2] = 0.f; s16[mt][1][3] = 0.f;
        }
        const uint32_t vb = kb + ATILE;
        uint32_t ap[2][4];
        #pragma unroll
        for (int mt = 0; mt < 2; mt++)
            #pragma unroll
            for (int q = 0; q < 4; q++) {
                int nt = q >> 1;
                ap[mt][q] = pack2h(s16[mt][nt][(q & 1) * 2],
                                   s16[mt][nt][(q & 1) * 2 + 1]);
            }
        #pragma unroll
        for (int np = 0; np < 4; np++) {
            uint32_t va_off = (rowin + (mat & 1) * 8) * AROW
                              + (np * 16 + (mat >> 1) * 8) * 2;
            uint32_t vhf[4];
            ldsm_x4_t(vhf, vb + va_off);
            #pragma unroll
            for (int mt = 0; mt < 2; mt++)
                #pragma unroll
                for (int h2 = 0; h2 < 2; h2++)
                    mma16816h(o[mt][np * 2 + h2], ap[mt],
                              vhf[2 * h2], vhf[2 * h2 + 1]);
        }
    }

    // ---- deferred row-sum reductions + epilogue (O -> single fp16)
    #pragma unroll
    for (int mt = 0; mt < 2; mt++) {
        l[mt][0] += __shfl_xor_sync(0xffffffffu, l[mt][0], 1);
        l[mt][0] += __shfl_xor_sync(0xffffffffu, l[mt][0], 2);
        l[mt][1] += __shfl_xor_sync(0xffffffffu, l[mt][1], 1);
        l[mt][1] += __shfl_xor_sync(0xffffffffu, l[mt][1], 2);
        float inv0 = 1.0f / l[mt][0], inv1 = 1.0f / l[mt][1];
        int y0 = tgm0 + mt * 16, y1 = y0 + 8;
        #pragma unroll
        for (int nt = 0; nt < 8; nt++) {
            int col = hx * 64 + nt * 8 + tig * 2;
            size_t i0 = (size_t)(y0 * BZ + bx) * E_ + col;
            *reinterpret_cast<uint32_t*>(&g_A16[i0]) =
                pack2h(o[mt][nt][0] * inv0, o[mt][nt][1] * inv0);
            size_t i1 = (size_t)(y1 * BZ + bx) * E_ + col;
            *reinterpret_cast<uint32_t*>(&g_A16[i1]) =
                pack2h(o[mt][nt][2] * inv1, o[mt][nt][3] * inv1);
        }
    }
}

// ---------------------------------------------------------------- host side
extern "C" void kernel_launch(void* const* d_in, const int* in_sizes, int n_in,
                              void* d_out, int out_size)
{
    (void)in_sizes; (void)n_in; (void)out_size;
    const float* query   = (const float*)d_in[0];
    const float* q_w     = (const float*)d_in[1];
    const float* q_b     = (const float*)d_in[2];
    const float* k_w     = (const float*)d_in[3];
    const float* k_b     = (const float*)d_in[4];
    const float* v_w     = (const float*)d_in[5];
    const float* v_b     = (const float*)d_in[6];
    const float* out_w   = (const float*)d_in[7];
    const float* out_b   = (const float*)d_in[8];
    const float* rel_emb = (const float*)d_in[9];
    const float* grep_w  = (const float*)d_in[10];
    const float* grep_b  = (const float*)d_in[11];
    const float* grep_a  = (const float*)d_in[12];
    const float* bias_k  = (const float*)d_in[13];
    const float* bias_v  = (const float*)d_in[14];
    float* out = (float*)d_out;

    void *pA, *pWh;
    cudaGetSymbolAddress(&pA,  g_A16);
    cudaGetSymbolAddress(&pWh, g_Wh16);

    __half* A16 = (__half*)pA;
    const size_t wsz = (size_t)E_ * E_;
    __half* Wh = (__half*)pWh;

    cudaFuncSetAttribute((const void*)gemm_qkv,
        cudaFuncAttributeMaxDynamicSharedMemorySize, GEMM_SMEM);
    cudaFuncSetAttribute((const void*)gemm_out,
        cudaFuncAttributeMaxDynamicSharedMemorySize, GEMM_SMEM);
    cudaFuncSetAttribute((const void*)attn_mma,
        cudaFuncAttributeMaxDynamicSharedMemorySize, ATTN_SMEM);

    prep_all<<<8208, 256>>>(query, q_w, k_w, v_w, out_w,
                            rel_emb, bias_k, bias_v);                  // 1
    gemm_qkv<<<dim3(24, 16), 512, GEMM_SMEM>>>(A16, q_b, k_b, v_b);    // 2
    attn_mma<<<dim3(8, 64), 128, ATTN_SMEM>>>(grep_w, grep_b, grep_a); // 3
    gemm_out<<<dim3(8, 16), 512, GEMM_SMEM>>>(                         // 4
        A16, Wh + 3 * wsz, out_b, out);
}